// round 4
// baseline (speedup 1.0000x reference)
#include <cuda_runtime.h>
#include <cuda_fp16.h>
#include <math.h>

#define Natoms 1024
#define Hdim   256
#define Ldim   512
#define NGs    50
#define NIs    3
#define Bmol   16
#define NGRID  384
#define CUT    5.0f
#define TR     16
#define WIN    11

typedef unsigned long long ull;

// scratch (no allocations allowed)
__device__ float  g_h[Natoms*Hdim];
__device__ __align__(16) __half g_hh[Natoms*Hdim];      // fp16 mirror of h
__device__ float  g_agg[Natoms*Hdim];
__device__ float  g_tmp[Natoms*Hdim];
__device__ float  g_G[NIs*NGRID*Hdim];                  // gelu hidden of table MLP
__device__ __align__(16) __half g_tab[NIs*NGRID*Hdim];  // fp16 filter tables
__device__ float  g_pool[Bmol*Hdim];
__device__ unsigned g_nbr[Natoms*Natoms];               // packed neighbor list
__device__ int      g_cnt[Natoms];

__device__ __forceinline__ float gelu_f(float x){
    return 0.5f*x*(1.0f+erff(x*0.70710678118654752f));
}
__device__ __forceinline__ void ffma2(ull& d, ull a, ull b){
    asm("fma.rn.f32x2 %0, %1, %2, %0;" : "+l"(d) : "l"(a), "l"(b));
}
__device__ __forceinline__ float2 unpk(ull v){
    float2 r; asm("mov.b64 {%0,%1}, %2;" : "=f"(r.x), "=f"(r.y) : "l"(v)); return r;
}

// ---------------------------------------------------------------- embedding
__global__ void k_embed(const int* __restrict__ z, const float* __restrict__ emb){
    int i=blockIdx.x, c=threadIdx.x;
    float v=emb[z[i]*Hdim+c];
    g_h[i*Hdim+c]=v;
    g_hh[i*Hdim+c]=__float2half(v);
}

// ------------------------------------------------ neighbor list (built once)
// packed: j(10) | r(9)<<10 | fq(13)<<19 ; r = round(t) clamped [1,NGRID-2], f=t-r in [-1,1]
__global__ void k_nbr(const float* __restrict__ pos){
    __shared__ int warp_cnt[8];
    int i=blockIdx.x, tid=threadIdx.x;
    float xi=pos[i*3+0], yi=pos[i*3+1], zi=pos[i*3+2];
    const float scale=(float)(NGRID-1)/CUT;
    int total=0;
    for(int base=0;base<Natoms;base+=256){
        int j=base+tid;
        float dx=pos[j*3+0]-xi;
        float dy=pos[j*3+1]-yi;
        float dz=pos[j*3+2]-zi;
        float d=sqrtf(dx*dx+dy*dy+dz*dz);
        bool keep=(j!=i)&&(d<CUT)&&(d>1e-6f);
        unsigned m=__ballot_sync(0xffffffffu,keep);
        if((tid&31)==0) warp_cnt[tid>>5]=__popc(m);
        __syncthreads();
        int off=total;
        int w=tid>>5;
        for(int ww=0;ww<w;ww++) off+=warp_cnt[ww];
        if(keep){
            int p=off+__popc(m&((1u<<(tid&31))-1u));
            float t=d*scale;
            int r=(int)(t+0.5f);
            if(r<1)r=1; if(r>NGRID-2)r=NGRID-2;
            float f=t-(float)r;
            int fq=(int)((f+1.0f)*4096.0f);
            if(fq<0)fq=0; if(fq>8191)fq=8191;
            g_nbr[i*Natoms+p]=(unsigned)j | ((unsigned)r<<10) | ((unsigned)fq<<19);
        }
        int bt=0;
        #pragma unroll
        for(int ww=0;ww<8;ww++) bt+=warp_cnt[ww];
        total+=bt;
        __syncthreads();
    }
    if(tid==0) g_cnt[i]=total;
}

// --------------------------------- table hidden: G = gelu(rbf @ fw1 + fb1)
__global__ void k_hidden(const float* __restrict__ fw1all, const float* __restrict__ fb1all){
    __shared__ float rbf[TR][WIN+1];
    __shared__ int s_base;
    int layer=blockIdx.y;
    const float* fw1=fw1all+layer*NGs*Hdim;
    const float* fb1=fb1all+layer*Hdim;
    int r0=blockIdx.x*TR, c=threadIdx.x;
    const float dstep  = CUT/(float)(NGRID-1);
    const float cstep  = CUT/(float)(NGs-1);
    const float inv2w2 = 1.0f/(2.0f*0.05f*0.05f);

    if(c==0){
        float dmid=((float)r0+7.5f)*dstep;
        int b0=(int)(dmid/cstep+0.5f)-(WIN/2);
        s_base=b0;
    }
    __syncthreads();
    int base=s_base;
    for(int t=c;t<TR*WIN;t+=256){
        int row=t/WIN, g=t%WIN;
        int gi=base+g;
        float d=(float)(r0+row)*dstep;
        float u=d-(float)gi*cstep;
        float v=expf(-u*u*inv2w2);
        rbf[row][g]=(gi>=0 && gi<NGs)?v:0.0f;
    }
    __syncthreads();
    float acc[TR];
    float b1=fb1[c];
    #pragma unroll
    for(int t=0;t<TR;t++) acc[t]=b1;
    #pragma unroll
    for(int g=0;g<WIN;g++){
        int gi=base+g;
        gi=(gi<0)?0:((gi>NGs-1)?NGs-1:gi);
        float w=fw1[gi*Hdim+c];
        #pragma unroll
        for(int t=0;t<TR;t++) acc[t]=fmaf(rbf[t][g],w,acc[t]);
    }
    float* G=g_G+layer*NGRID*Hdim;
    #pragma unroll
    for(int t=0;t<TR;t++) G[(r0+t)*Hdim+c]=gelu_f(acc[t]);
}

// --------------------------- GEMM  C = act(A@W + b) [+Res], BMx64 tiles
template<bool GELU,bool RES,bool HALF_OUT,bool WRITEH,bool LAYERED,int MROWS,int BM>
__global__ void __launch_bounds__(256) k_gemm(const float* __restrict__ A,
                       const float* __restrict__ W,
                       const float* __restrict__ bias,
                       const float* __restrict__ Res,
                       float* __restrict__ Cf, __half* __restrict__ Ch){
    constexpr int MU=BM/16;
    __shared__ ull As2[8][BM+2];
    __shared__ ull Bs2[8][66];
    if(LAYERED){
        int L=blockIdx.z;
        A   += (size_t)L*MROWS*Hdim;
        W   += (size_t)L*Hdim*Hdim;
        bias+= (size_t)L*Hdim;
        if(HALF_OUT) Ch += (size_t)L*MROWS*Hdim;
        else         Cf += (size_t)L*MROWS*Hdim;
    }
    int m0=blockIdx.x*BM, n0=blockIdx.y*64;
    int tid=threadIdx.x;
    int tm=tid>>4;
    int tn=tid&15;
    ull acc[MU][4];
    #pragma unroll
    for(int u=0;u<MU;u++)
        #pragma unroll
        for(int v=0;v<4;v++) acc[u][v]=0ull;

    int ar=tid>>2, ak=(tid&3)<<2;
    int bkp=tid>>5, bn2=(tid&31)<<1;

    for(int k0=0;k0<Hdim;k0+=16){
        if(BM==64 || tid<128){
            float4 av=*reinterpret_cast<const float4*>(&A[(m0+ar)*Hdim+k0+ak]);
            ull lo, hi;
            asm("mov.b64 %0, {%1,%2};":"=l"(lo):"f"(av.x),"f"(av.y));
            asm("mov.b64 %0, {%1,%2};":"=l"(hi):"f"(av.z),"f"(av.w));
            As2[(ak>>1)+0][ar]=lo;
            As2[(ak>>1)+1][ar]=hi;
        }
        {
            float2 w0=*reinterpret_cast<const float2*>(&W[(k0+2*bkp  )*Hdim+n0+bn2]);
            float2 w1=*reinterpret_cast<const float2*>(&W[(k0+2*bkp+1)*Hdim+n0+bn2]);
            ull p0,p1;
            asm("mov.b64 %0, {%1,%2};":"=l"(p0):"f"(w0.x),"f"(w1.x));
            asm("mov.b64 %0, {%1,%2};":"=l"(p1):"f"(w0.y),"f"(w1.y));
            Bs2[bkp][bn2+0]=p0;
            Bs2[bkp][bn2+1]=p1;
        }
        __syncthreads();
        #pragma unroll
        for(int kp=0;kp<8;kp++){
            ull a[MU],b[4];
            #pragma unroll
            for(int u=0;u<MU;u++) a[u]=As2[kp][tm*MU+u];
            #pragma unroll
            for(int v=0;v<4;v++) b[v]=Bs2[kp][tn+v*16];
            #pragma unroll
            for(int u=0;u<MU;u++)
                #pragma unroll
                for(int v=0;v<4;v++) ffma2(acc[u][v],a[u],b[v]);
        }
        __syncthreads();
    }
    #pragma unroll
    for(int u=0;u<MU;u++){
        int row=m0+tm*MU+u;
        #pragma unroll
        for(int v=0;v<4;v++){
            int col=n0+tn+v*16;
            float2 s=unpk(acc[u][v]);
            float x=s.x+s.y+bias[col];
            if(GELU) x=gelu_f(x);
            if(RES)  x+=Res[row*Hdim+col];
            if(HALF_OUT) Ch[row*Hdim+col]=__float2half(x);
            else         Cf[row*Hdim+col]=x;
            if(WRITEH)   g_hh[row*Hdim+col]=__float2half(x);
        }
    }
}

// ------------------- neighbor aggregation: smem table + quadratic interp
// grid 128 CTAs x 512 thr; 4 atom-slots of 128 threads; 8 atoms per CTA.
__global__ void __launch_bounds__(512) k_agg(const __half2* __restrict__ tab){
    extern __shared__ __half2 tab_s[];     // NGRID*128 half2 = 192 KB
    int tid=threadIdx.x;
    {
        const uint4* src=reinterpret_cast<const uint4*>(tab);
        uint4* dst=reinterpret_cast<uint4*>(tab_s);
        #pragma unroll
        for(int idx=tid;idx<(NGRID*Hdim*2)/16;idx+=512) dst[idx]=src[idx];
    }
    __syncthreads();
    int s=tid>>7;          // atom slot 0..3
    int c=tid&127;         // half2 channel
    const __half2* __restrict__ hh=reinterpret_cast<const __half2*>(g_hh);
    for(int a=0;a<2;a++){
        int i=blockIdx.x*8 + s*2 + a;
        int total=g_cnt[i];
        const unsigned* __restrict__ lst=g_nbr+i*Natoms;
        float ax=0.f, ay=0.f;
        #pragma unroll 4
        for(int n=0;n<total;n++){
            unsigned p=__ldg(&lst[n]);
            int j=p&1023;
            int r=(p>>10)&511;
            float f=(float)(p>>19)*(1.0f/4096.0f)-1.0f;
            float2 m=__half22float2(tab_s[(r-1)*128+c]);
            float2 z=__half22float2(tab_s[ r   *128+c]);
            float2 q=__half22float2(tab_s[(r+1)*128+c]);
            float2 hv=__half22float2(__ldg(&hh[j*128+c]));
            float bx=0.5f*(q.x-m.x),      by=0.5f*(q.y-m.y);
            float cx=0.5f*(q.x+m.x)-z.x,  cy=0.5f*(q.y+m.y)-z.y;
            float wx=fmaf(f,fmaf(f,cx,bx),z.x);
            float wy=fmaf(f,fmaf(f,cy,by),z.y);
            ax=fmaf(wx,hv.x,ax);
            ay=fmaf(wy,hv.y,ay);
        }
        reinterpret_cast<float2*>(g_agg)[i*128+c]=make_float2(ax,ay);
    }
}

// ---------------------------------------------------------------- pooling
__global__ void k_pool(const int* __restrict__ batch){
    int b=blockIdx.x, c=threadIdx.x;
    float s=0.f;
    #pragma unroll 8
    for(int i=0;i<Natoms;i++){
        s += (batch[i]==b) ? g_h[i*Hdim+c] : 0.f;
    }
    g_pool[b*Hdim+c]=s;
}

// ------------------------------------------------- projection head + layernorm
__global__ void k_head(const float* __restrict__ pw1,const float* __restrict__ pb1,
                       const float* __restrict__ pw2,const float* __restrict__ pb2,
                       const float* __restrict__ lng,const float* __restrict__ lnb,
                       float* __restrict__ out){
    __shared__ float pv[Hdim];
    __shared__ float tv[Hdim];
    __shared__ float xv[Ldim];
    __shared__ float red[8];
    __shared__ float s_mu, s_inv;
    int b=blockIdx.x, tid=threadIdx.x;
    pv[tid]=g_pool[b*Hdim+tid];
    __syncthreads();
    float a=pb1[tid];
    for(int k=0;k<Hdim;k++) a=fmaf(pv[k],pw1[k*Hdim+tid],a);
    tv[tid]=gelu_f(a);
    __syncthreads();
    for(int o=tid;o<Ldim;o+=256){
        float x=pb2[o];
        for(int k=0;k<Hdim;k++) x=fmaf(tv[k],pw2[k*Ldim+o],x);
        xv[o]=x;
    }
    __syncthreads();
    float s=xv[tid]+xv[tid+256];
    for(int d=16;d>0;d>>=1) s+=__shfl_down_sync(0xffffffffu,s,d);
    if((tid&31)==0) red[tid>>5]=s;
    __syncthreads();
    if(tid==0){
        float t=0.f; for(int w=0;w<8;w++) t+=red[w];
        s_mu=t/(float)Ldim;
    }
    __syncthreads();
    float mu=s_mu;
    float d0=xv[tid]-mu, d1=xv[tid+256]-mu;
    float s2=d0*d0+d1*d1;
    for(int d=16;d>0;d>>=1) s2+=__shfl_down_sync(0xffffffffu,s2,d);
    if((tid&31)==0) red[tid>>5]=s2;
    __syncthreads();
    if(tid==0){
        float t=0.f; for(int w=0;w<8;w++) t+=red[w];
        s_inv=1.0f/sqrtf(t/(float)Ldim + 1e-5f);
    }
    __syncthreads();
    float inv=s_inv;
    out[b*Ldim+tid]     =(xv[tid]-mu)*inv*lng[tid]+lnb[tid];
    out[b*Ldim+tid+256] =(xv[tid+256]-mu)*inv*lng[tid+256]+lnb[tid+256];
}

// ------------------------------------------------------------------ launcher
extern "C" void kernel_launch(void* const* d_in, const int* in_sizes, int n_in,
                              void* d_out, int out_size){
    const int*   z    =(const int*)  d_in[0];
    const float* pos  =(const float*)d_in[1];
    const int*   batch=(const int*)  d_in[2];
    const float* emb  =(const float*)d_in[3];
    const float* fw1  =(const float*)d_in[4];
    const float* fb1  =(const float*)d_in[5];
    const float* fw2  =(const float*)d_in[6];
    const float* fb2  =(const float*)d_in[7];
    const float* aw1  =(const float*)d_in[8];
    const float* ab1  =(const float*)d_in[9];
    const float* aw2  =(const float*)d_in[10];
    const float* ab2  =(const float*)d_in[11];
    const float* pw1  =(const float*)d_in[12];
    const float* pb1  =(const float*)d_in[13];
    const float* pw2  =(const float*)d_in[14];
    const float* pb2  =(const float*)d_in[15];
    const float* lng  =(const float*)d_in[16];
    const float* lnb  =(const float*)d_in[17];
    float* out=(float*)d_out;

    float *pagg,*ptmp,*ph,*pG;
    __half *ptab;
    cudaGetSymbolAddress((void**)&pagg,g_agg);
    cudaGetSymbolAddress((void**)&ptmp,g_tmp);
    cudaGetSymbolAddress((void**)&ph,  g_h);
    cudaGetSymbolAddress((void**)&pG,  g_G);
    cudaGetSymbolAddress((void**)&ptab,g_tab);

    const int TAB_SMEM = NGRID*Hdim*2;   // 196608 B
    cudaFuncSetAttribute(k_agg, cudaFuncAttributeMaxDynamicSharedMemorySize, TAB_SMEM);

    k_embed<<<Natoms,Hdim>>>(z,emb);
    k_nbr<<<Natoms,256>>>(pos);
    // build all 3 layers' filter tables upfront
    k_hidden<<<dim3(NGRID/TR,NIs),Hdim>>>(fw1,fb1);
    k_gemm<false,false,true ,false,true ,NGRID,64><<<dim3(NGRID/64,Hdim/64,NIs),256>>>(pG, fw2, fb2, nullptr, nullptr, ptab);
    for(int l=0;l<NIs;l++){
        k_agg<<<Natoms/8,512,TAB_SMEM>>>(reinterpret_cast<const __half2*>(ptab)+(size_t)l*NGRID*Hdim/2);
        k_gemm<true ,false,false,false,false,Natoms,32><<<dim3(Natoms/32,Hdim/64),256>>>(pagg, aw1+l*Hdim*Hdim, ab1+l*Hdim, nullptr, ptmp, nullptr);
        k_gemm<false,true ,false,true ,false,Natoms,32><<<dim3(Natoms/32,Hdim/64),256>>>(ptmp, aw2+l*Hdim*Hdim, ab2+l*Hdim, ph, ph, nullptr);
    }
    k_pool<<<Bmol,Hdim>>>(batch);
    k_head<<<Bmol,Hdim>>>(pw1,pb1,pw2,pb2,lng,lnb,out);
}

// round 5
// speedup vs baseline: 1.3820x; 1.3820x over previous
#include <cuda_runtime.h>
#include <cuda_fp16.h>
#include <math.h>

#define Natoms 1024
#define Hdim   256
#define Ldim   512
#define NGs    50
#define NIs    3
#define Bmol   16
#define NGRID  384
#define CUT    5.0f
#define TR     16
#define WIN    11

typedef unsigned long long ull;

// scratch (no allocations allowed)
__device__ float  g_h[Natoms*Hdim];
__device__ __align__(16) __half g_hh[Natoms*Hdim];      // fp16 mirror of h
__device__ float  g_agg[Natoms*Hdim];
__device__ float  g_tmp[Natoms*Hdim];
__device__ float  g_G[NIs*NGRID*Hdim];                  // gelu hidden of table MLP
__device__ __align__(16) __half g_tab[NIs*NGRID*Hdim];  // fp16 filter tables
__device__ float  g_pool[Bmol*Hdim];
__device__ unsigned g_nbr[Natoms*Natoms];               // packed neighbor list
__device__ int      g_cnt[Natoms];

__device__ __forceinline__ float gelu_f(float x){
    return 0.5f*x*(1.0f+erff(x*0.70710678118654752f));
}
__device__ __forceinline__ void ffma2(ull& d, ull a, ull b){
    asm("fma.rn.f32x2 %0, %1, %2, %0;" : "+l"(d) : "l"(a), "l"(b));
}
__device__ __forceinline__ float2 unpk(ull v){
    float2 r; asm("mov.b64 {%0,%1}, %2;" : "=f"(r.x), "=f"(r.y) : "l"(v)); return r;
}

// ---------------------------------------------------------------- embedding
__global__ void k_embed(const int* __restrict__ z, const float* __restrict__ emb){
    int i=blockIdx.x, c=threadIdx.x;
    float v=emb[z[i]*Hdim+c];
    g_h[i*Hdim+c]=v;
    g_hh[i*Hdim+c]=__float2half(v);
}

// ------------------------------------------------ neighbor list (built once)
// packed: j(10) | r(9)<<10 | fq(13)<<19 ; r = round(t) clamped [1,NGRID-2], f=t-r in [-1,1]
__global__ void k_nbr(const float* __restrict__ pos){
    __shared__ int warp_cnt[8];
    int i=blockIdx.x, tid=threadIdx.x;
    float xi=pos[i*3+0], yi=pos[i*3+1], zi=pos[i*3+2];
    const float scale=(float)(NGRID-1)/CUT;
    int total=0;
    for(int base=0;base<Natoms;base+=256){
        int j=base+tid;
        float dx=pos[j*3+0]-xi;
        float dy=pos[j*3+1]-yi;
        float dz=pos[j*3+2]-zi;
        float d=sqrtf(dx*dx+dy*dy+dz*dz);
        bool keep=(j!=i)&&(d<CUT)&&(d>1e-6f);
        unsigned m=__ballot_sync(0xffffffffu,keep);
        if((tid&31)==0) warp_cnt[tid>>5]=__popc(m);
        __syncthreads();
        int off=total;
        int w=tid>>5;
        for(int ww=0;ww<w;ww++) off+=warp_cnt[ww];
        if(keep){
            int p=off+__popc(m&((1u<<(tid&31))-1u));
            float t=d*scale;
            int r=(int)(t+0.5f);
            if(r<1)r=1; if(r>NGRID-2)r=NGRID-2;
            float f=t-(float)r;
            int fq=(int)((f+1.0f)*4096.0f);
            if(fq<0)fq=0; if(fq>8191)fq=8191;
            g_nbr[i*Natoms+p]=(unsigned)j | ((unsigned)r<<10) | ((unsigned)fq<<19);
        }
        int bt=0;
        #pragma unroll
        for(int ww=0;ww<8;ww++) bt+=warp_cnt[ww];
        total+=bt;
        __syncthreads();
    }
    if(tid==0) g_cnt[i]=total;
}

// --------------------------------- table hidden: G = gelu(rbf @ fw1 + fb1)
__global__ void k_hidden(const float* __restrict__ fw1all, const float* __restrict__ fb1all){
    __shared__ float rbf[TR][WIN+1];
    __shared__ int s_base;
    int layer=blockIdx.y;
    const float* fw1=fw1all+layer*NGs*Hdim;
    const float* fb1=fb1all+layer*Hdim;
    int r0=blockIdx.x*TR, c=threadIdx.x;
    const float dstep  = CUT/(float)(NGRID-1);
    const float cstep  = CUT/(float)(NGs-1);
    const float inv2w2 = 1.0f/(2.0f*0.05f*0.05f);

    if(c==0){
        float dmid=((float)r0+7.5f)*dstep;
        int b0=(int)(dmid/cstep+0.5f)-(WIN/2);
        s_base=b0;
    }
    __syncthreads();
    int base=s_base;
    for(int t=c;t<TR*WIN;t+=256){
        int row=t/WIN, g=t%WIN;
        int gi=base+g;
        float d=(float)(r0+row)*dstep;
        float u=d-(float)gi*cstep;
        float v=expf(-u*u*inv2w2);
        rbf[row][g]=(gi>=0 && gi<NGs)?v:0.0f;
    }
    __syncthreads();
    float acc[TR];
    float b1=fb1[c];
    #pragma unroll
    for(int t=0;t<TR;t++) acc[t]=b1;
    #pragma unroll
    for(int g=0;g<WIN;g++){
        int gi=base+g;
        gi=(gi<0)?0:((gi>NGs-1)?NGs-1:gi);
        float w=fw1[gi*Hdim+c];
        #pragma unroll
        for(int t=0;t<TR;t++) acc[t]=fmaf(rbf[t][g],w,acc[t]);
    }
    float* G=g_G+layer*NGRID*Hdim;
    #pragma unroll
    for(int t=0;t<TR;t++) G[(r0+t)*Hdim+c]=gelu_f(acc[t]);
}

// --------------------------- GEMM  C = act(A@W + b) [+Res], BMx64 tiles
template<bool GELU,bool RES,bool HALF_OUT,bool WRITEH,bool LAYERED,int MROWS,int BM>
__global__ void __launch_bounds__(256) k_gemm(const float* __restrict__ A,
                       const float* __restrict__ W,
                       const float* __restrict__ bias,
                       const float* __restrict__ Res,
                       float* __restrict__ Cf, __half* __restrict__ Ch){
    constexpr int MU=BM/16;
    __shared__ ull As2[8][BM+2];
    __shared__ ull Bs2[8][66];
    if(LAYERED){
        int L=blockIdx.z;
        A   += (size_t)L*MROWS*Hdim;
        W   += (size_t)L*Hdim*Hdim;
        bias+= (size_t)L*Hdim;
        if(HALF_OUT) Ch += (size_t)L*MROWS*Hdim;
        else         Cf += (size_t)L*MROWS*Hdim;
    }
    int m0=blockIdx.x*BM, n0=blockIdx.y*64;
    int tid=threadIdx.x;
    int tm=tid>>4;
    int tn=tid&15;
    ull acc[MU][4];
    #pragma unroll
    for(int u=0;u<MU;u++)
        #pragma unroll
        for(int v=0;v<4;v++) acc[u][v]=0ull;

    int ar=tid>>2, ak=(tid&3)<<2;
    int bkp=tid>>5, bn2=(tid&31)<<1;

    for(int k0=0;k0<Hdim;k0+=16){
        if(BM==64 || tid<128){
            float4 av=*reinterpret_cast<const float4*>(&A[(m0+ar)*Hdim+k0+ak]);
            ull lo, hi;
            asm("mov.b64 %0, {%1,%2};":"=l"(lo):"f"(av.x),"f"(av.y));
            asm("mov.b64 %0, {%1,%2};":"=l"(hi):"f"(av.z),"f"(av.w));
            As2[(ak>>1)+0][ar]=lo;
            As2[(ak>>1)+1][ar]=hi;
        }
        {
            float2 w0=*reinterpret_cast<const float2*>(&W[(k0+2*bkp  )*Hdim+n0+bn2]);
            float2 w1=*reinterpret_cast<const float2*>(&W[(k0+2*bkp+1)*Hdim+n0+bn2]);
            ull p0,p1;
            asm("mov.b64 %0, {%1,%2};":"=l"(p0):"f"(w0.x),"f"(w1.x));
            asm("mov.b64 %0, {%1,%2};":"=l"(p1):"f"(w0.y),"f"(w1.y));
            Bs2[bkp][bn2+0]=p0;
            Bs2[bkp][bn2+1]=p1;
        }
        __syncthreads();
        #pragma unroll
        for(int kp=0;kp<8;kp++){
            ull a[MU],b[4];
            #pragma unroll
            for(int u=0;u<MU;u++) a[u]=As2[kp][tm*MU+u];
            #pragma unroll
            for(int v=0;v<4;v++) b[v]=Bs2[kp][tn+v*16];
            #pragma unroll
            for(int u=0;u<MU;u++)
                #pragma unroll
                for(int v=0;v<4;v++) ffma2(acc[u][v],a[u],b[v]);
        }
        __syncthreads();
    }
    #pragma unroll
    for(int u=0;u<MU;u++){
        int row=m0+tm*MU+u;
        #pragma unroll
        for(int v=0;v<4;v++){
            int col=n0+tn+v*16;
            float2 s=unpk(acc[u][v]);
            float x=s.x+s.y+bias[col];
            if(GELU) x=gelu_f(x);
            if(RES)  x+=Res[row*Hdim+col];
            if(HALF_OUT) Ch[row*Hdim+col]=__float2half(x);
            else         Cf[row*Hdim+col]=x;
            if(WRITEH)   g_hh[row*Hdim+col]=__float2half(x);
        }
    }
}

// ------------------- neighbor aggregation v2: smem table, quadratic interp,
// 1024 threads (32 warps), 8 slots x 1 atom, explicit 4-way gather pipeline.
__device__ __forceinline__ void agg_step(unsigned p, __half2 hv,
                                         const __half2* __restrict__ tab_s,
                                         int c, float& ax, float& ay){
    int r=(p>>10)&511;
    float f=(float)(p>>19)*(1.0f/4096.0f)-1.0f;
    const __half2* base=tab_s + r*128 + c;
    float2 m=__half22float2(base[-128]);
    float2 z=__half22float2(base[0]);
    float2 q=__half22float2(base[128]);
    float2 hf=__half22float2(hv);
    float bx=0.5f*(q.x-m.x),      by=0.5f*(q.y-m.y);
    float cx=0.5f*(q.x+m.x)-z.x,  cy=0.5f*(q.y+m.y)-z.y;
    float wx=fmaf(f,fmaf(f,cx,bx),z.x);
    float wy=fmaf(f,fmaf(f,cy,by),z.y);
    ax=fmaf(wx,hf.x,ax);
    ay=fmaf(wy,hf.y,ay);
}

__global__ void __launch_bounds__(1024,1) k_agg(const __half2* __restrict__ tab){
    extern __shared__ __half2 tab_s[];     // NGRID*128 half2 = 192 KB
    int tid=threadIdx.x;
    {
        const uint4* src=reinterpret_cast<const uint4*>(tab);
        uint4* dst=reinterpret_cast<uint4*>(tab_s);
        #pragma unroll
        for(int idx=tid;idx<(NGRID*Hdim*2)/16;idx+=1024) dst[idx]=src[idx];
    }
    __syncthreads();
    int s=tid>>7;          // slot 0..7, one atom each
    int c=tid&127;         // half2 channel
    const __half2* __restrict__ hh=reinterpret_cast<const __half2*>(g_hh);
    int i=blockIdx.x*8 + s;
    int total=g_cnt[i];
    const unsigned* __restrict__ lst=g_nbr+i*Natoms;
    float ax=0.f, ay=0.f;
    int n=0;
    for(; n+4<=total; n+=4){
        // gather phase: 4 independent LDG chains in flight
        unsigned p0=__ldg(lst+n+0);
        unsigned p1=__ldg(lst+n+1);
        unsigned p2=__ldg(lst+n+2);
        unsigned p3=__ldg(lst+n+3);
        __half2 h0=__ldg(hh+(p0&1023)*128+c);
        __half2 h1=__ldg(hh+(p1&1023)*128+c);
        __half2 h2=__ldg(hh+(p2&1023)*128+c);
        __half2 h3=__ldg(hh+(p3&1023)*128+c);
        agg_step(p0,h0,tab_s,c,ax,ay);
        agg_step(p1,h1,tab_s,c,ax,ay);
        agg_step(p2,h2,tab_s,c,ax,ay);
        agg_step(p3,h3,tab_s,c,ax,ay);
    }
    for(; n<total; n++){
        unsigned p=__ldg(lst+n);
        __half2 hv=__ldg(hh+(p&1023)*128+c);
        agg_step(p,hv,tab_s,c,ax,ay);
    }
    reinterpret_cast<float2*>(g_agg)[i*128+c]=make_float2(ax,ay);
}

// ---------------------------------------------------------------- pooling
__global__ void k_pool(const int* __restrict__ batch){
    int b=blockIdx.x, c=threadIdx.x;
    float s=0.f;
    #pragma unroll 8
    for(int i=0;i<Natoms;i++){
        s += (batch[i]==b) ? g_h[i*Hdim+c] : 0.f;
    }
    g_pool[b*Hdim+c]=s;
}

// ------------------------------------------------- projection head + layernorm
__global__ void k_head(const float* __restrict__ pw1,const float* __restrict__ pb1,
                       const float* __restrict__ pw2,const float* __restrict__ pb2,
                       const float* __restrict__ lng,const float* __restrict__ lnb,
                       float* __restrict__ out){
    __shared__ float pv[Hdim];
    __shared__ float tv[Hdim];
    __shared__ float xv[Ldim];
    __shared__ float red[8];
    __shared__ float s_mu, s_inv;
    int b=blockIdx.x, tid=threadIdx.x;
    pv[tid]=g_pool[b*Hdim+tid];
    __syncthreads();
    float a=pb1[tid];
    for(int k=0;k<Hdim;k++) a=fmaf(pv[k],pw1[k*Hdim+tid],a);
    tv[tid]=gelu_f(a);
    __syncthreads();
    for(int o=tid;o<Ldim;o+=256){
        float x=pb2[o];
        for(int k=0;k<Hdim;k++) x=fmaf(tv[k],pw2[k*Ldim+o],x);
        xv[o]=x;
    }
    __syncthreads();
    float s=xv[tid]+xv[tid+256];
    for(int d=16;d>0;d>>=1) s+=__shfl_down_sync(0xffffffffu,s,d);
    if((tid&31)==0) red[tid>>5]=s;
    __syncthreads();
    if(tid==0){
        float t=0.f; for(int w=0;w<8;w++) t+=red[w];
        s_mu=t/(float)Ldim;
    }
    __syncthreads();
    float mu=s_mu;
    float d0=xv[tid]-mu, d1=xv[tid+256]-mu;
    float s2=d0*d0+d1*d1;
    for(int d=16;d>0;d>>=1) s2+=__shfl_down_sync(0xffffffffu,s2,d);
    if((tid&31)==0) red[tid>>5]=s2;
    __syncthreads();
    if(tid==0){
        float t=0.f; for(int w=0;w<8;w++) t+=red[w];
        s_inv=1.0f/sqrtf(t/(float)Ldim + 1e-5f);
    }
    __syncthreads();
    float inv=s_inv;
    out[b*Ldim+tid]     =(xv[tid]-mu)*inv*lng[tid]+lnb[tid];
    out[b*Ldim+tid+256] =(xv[tid+256]-mu)*inv*lng[tid+256]+lnb[tid+256];
}

// ------------------------------------------------------------------ launcher
extern "C" void kernel_launch(void* const* d_in, const int* in_sizes, int n_in,
                              void* d_out, int out_size){
    const int*   z    =(const int*)  d_in[0];
    const float* pos  =(const float*)d_in[1];
    const int*   batch=(const int*)  d_in[2];
    const float* emb  =(const float*)d_in[3];
    const float* fw1  =(const float*)d_in[4];
    const float* fb1  =(const float*)d_in[5];
    const float* fw2  =(const float*)d_in[6];
    const float* fb2  =(const float*)d_in[7];
    const float* aw1  =(const float*)d_in[8];
    const float* ab1  =(const float*)d_in[9];
    const float* aw2  =(const float*)d_in[10];
    const float* ab2  =(const float*)d_in[11];
    const float* pw1  =(const float*)d_in[12];
    const float* pb1  =(const float*)d_in[13];
    const float* pw2  =(const float*)d_in[14];
    const float* pb2  =(const float*)d_in[15];
    const float* lng  =(const float*)d_in[16];
    const float* lnb  =(const float*)d_in[17];
    float* out=(float*)d_out;

    float *pagg,*ptmp,*ph,*pG;
    __half *ptab;
    cudaGetSymbolAddress((void**)&pagg,g_agg);
    cudaGetSymbolAddress((void**)&ptmp,g_tmp);
    cudaGetSymbolAddress((void**)&ph,  g_h);
    cudaGetSymbolAddress((void**)&pG,  g_G);
    cudaGetSymbolAddress((void**)&ptab,g_tab);

    const int TAB_SMEM = NGRID*Hdim*2;   // 196608 B
    cudaFuncSetAttribute(k_agg, cudaFuncAttributeMaxDynamicSharedMemorySize, TAB_SMEM);

    k_embed<<<Natoms,Hdim>>>(z,emb);
    k_nbr<<<Natoms,256>>>(pos);
    // build all 3 layers' filter tables upfront (BM=32 -> 144 CTAs)
    k_hidden<<<dim3(NGRID/TR,NIs),Hdim>>>(fw1,fb1);
    k_gemm<false,false,true ,false,true ,NGRID,32><<<dim3(NGRID/32,Hdim/64,NIs),256>>>(pG, fw2, fb2, nullptr, nullptr, ptab);
    for(int l=0;l<NIs;l++){
        k_agg<<<Natoms/8,1024,TAB_SMEM>>>(reinterpret_cast<const __half2*>(ptab)+(size_t)l*NGRID*Hdim/2);
        k_gemm<true ,false,false,false,false,Natoms,32><<<dim3(Natoms/32,Hdim/64),256>>>(pagg, aw1+l*Hdim*Hdim, ab1+l*Hdim, nullptr, ptmp, nullptr);
        k_gemm<false,true ,false,true ,false,Natoms,32><<<dim3(Natoms/32,Hdim/64),256>>>(ptmp, aw2+l*Hdim*Hdim, ab2+l*Hdim, ph, ph, nullptr);
    }
    k_pool<<<Bmol,Hdim>>>(batch);
    k_head<<<Bmol,Hdim>>>(pw1,pb1,pw2,pb2,lng,lnb,out);
}

// round 6
// speedup vs baseline: 1.5966x; 1.1553x over previous
#include <cuda_runtime.h>
#include <cuda_fp16.h>
#include <math.h>

#define Natoms 1024
#define Hdim   256
#define Ldim   512
#define NGs    50
#define NIs    3
#define Bmol   16
#define NGRID  384
#define CUT    5.0f
#define TR     16
#define WIN    11

typedef unsigned long long ull;

// scratch (no allocations allowed)
__device__ float  g_h[Natoms*Hdim];
__device__ __align__(16) __half g_hh[Natoms*Hdim];      // fp16 mirror of h
__device__ __align__(16) __half g_aggh[Natoms*Hdim];    // fp16 aggregation out
__device__ __align__(16) __half g_tmph[Natoms*Hdim];    // fp16 gemm1 out
__device__ __align__(16) __half g_Gh[NIs*NGRID*Hdim];   // fp16 gelu hidden of table MLP
__device__ __align__(16) __half g_tab[NIs*NGRID*Hdim];  // fp16 filter tables
__device__ __align__(16) __half g_fw2h[NIs*Hdim*Hdim];
__device__ __align__(16) __half g_aw1h[NIs*Hdim*Hdim];
__device__ __align__(16) __half g_aw2h[NIs*Hdim*Hdim];
__device__ float  g_pool[Bmol*Hdim];
__device__ unsigned g_nbr[Natoms*Natoms];               // packed neighbor list
__device__ int      g_cnt[Natoms];

__device__ __forceinline__ float gelu_f(float x){
    return 0.5f*x*(1.0f+erff(x*0.70710678118654752f));
}
__device__ __forceinline__ unsigned smem_u32(const void* p){
    return (unsigned)__cvta_generic_to_shared(p);
}
__device__ __forceinline__ void ldsm_x4(unsigned& r0,unsigned& r1,unsigned& r2,unsigned& r3,unsigned addr){
    asm volatile("ldmatrix.sync.aligned.m8n8.x4.shared.b16 {%0,%1,%2,%3}, [%4];"
        : "=r"(r0),"=r"(r1),"=r"(r2),"=r"(r3) : "r"(addr));
}
__device__ __forceinline__ void ldsm_x4t(unsigned& r0,unsigned& r1,unsigned& r2,unsigned& r3,unsigned addr){
    asm volatile("ldmatrix.sync.aligned.m8n8.x4.trans.shared.b16 {%0,%1,%2,%3}, [%4];"
        : "=r"(r0),"=r"(r1),"=r"(r2),"=r"(r3) : "r"(addr));
}
__device__ __forceinline__ void hmma(float* c, unsigned a0,unsigned a1,unsigned a2,unsigned a3,
                                     unsigned b0,unsigned b1){
    asm volatile("mma.sync.aligned.m16n8k16.row.col.f32.f16.f16.f32 "
        "{%0,%1,%2,%3}, {%4,%5,%6,%7}, {%8,%9}, {%0,%1,%2,%3};"
        : "+f"(c[0]),"+f"(c[1]),"+f"(c[2]),"+f"(c[3])
        : "r"(a0),"r"(a1),"r"(a2),"r"(a3),"r"(b0),"r"(b1));
}

// ---------------------------------------------------------------- embedding
__global__ void k_embed(const int* __restrict__ z, const float* __restrict__ emb){
    int i=blockIdx.x, c=threadIdx.x;
    float v=emb[z[i]*Hdim+c];
    g_h[i*Hdim+c]=v;
    g_hh[i*Hdim+c]=__float2half(v);
}

// ----------------------------------------- weight conversion to fp16 (once)
__global__ void k_cvt(const float* __restrict__ fw2, const float* __restrict__ aw1,
                      const float* __restrict__ aw2){
    int idx=blockIdx.x*1024+threadIdx.x;      // NIs*Hdim*Hdim = 196608
    g_fw2h[idx]=__float2half(fw2[idx]);
    g_aw1h[idx]=__float2half(aw1[idx]);
    g_aw2h[idx]=__float2half(aw2[idx]);
}

// ------------------------------------------------ neighbor list (built once)
// packed: j(10) | r(9)<<10 | fq(13)<<19 ; r = round(t) clamped [1,NGRID-2], f=t-r in [-1,1]
__global__ void k_nbr(const float* __restrict__ pos){
    __shared__ int warp_cnt[8];
    int i=blockIdx.x, tid=threadIdx.x;
    float xi=pos[i*3+0], yi=pos[i*3+1], zi=pos[i*3+2];
    const float scale=(float)(NGRID-1)/CUT;
    int total=0;
    for(int base=0;base<Natoms;base+=256){
        int j=base+tid;
        float dx=pos[j*3+0]-xi;
        float dy=pos[j*3+1]-yi;
        float dz=pos[j*3+2]-zi;
        float d=sqrtf(dx*dx+dy*dy+dz*dz);
        bool keep=(j!=i)&&(d<CUT)&&(d>1e-6f);
        unsigned m=__ballot_sync(0xffffffffu,keep);
        if((tid&31)==0) warp_cnt[tid>>5]=__popc(m);
        __syncthreads();
        int off=total;
        int w=tid>>5;
        for(int ww=0;ww<w;ww++) off+=warp_cnt[ww];
        if(keep){
            int p=off+__popc(m&((1u<<(tid&31))-1u));
            float t=d*scale;
            int r=(int)(t+0.5f);
            if(r<1)r=1; if(r>NGRID-2)r=NGRID-2;
            float f=t-(float)r;
            int fq=(int)((f+1.0f)*4096.0f);
            if(fq<0)fq=0; if(fq>8191)fq=8191;
            g_nbr[i*Natoms+p]=(unsigned)j | ((unsigned)r<<10) | ((unsigned)fq<<19);
        }
        int bt=0;
        #pragma unroll
        for(int ww=0;ww<8;ww++) bt+=warp_cnt[ww];
        total+=bt;
        __syncthreads();
    }
    if(tid==0) g_cnt[i]=total;
}

// --------------------------------- table hidden: G = gelu(rbf @ fw1 + fb1), fp16 out
__global__ void k_hidden(const float* __restrict__ fw1all, const float* __restrict__ fb1all){
    __shared__ float rbf[TR][WIN+1];
    __shared__ int s_base;
    int layer=blockIdx.y;
    const float* fw1=fw1all+layer*NGs*Hdim;
    const float* fb1=fb1all+layer*Hdim;
    int r0=blockIdx.x*TR, c=threadIdx.x;
    const float dstep  = CUT/(float)(NGRID-1);
    const float cstep  = CUT/(float)(NGs-1);
    const float inv2w2 = 1.0f/(2.0f*0.05f*0.05f);

    if(c==0){
        float dmid=((float)r0+7.5f)*dstep;
        int b0=(int)(dmid/cstep+0.5f)-(WIN/2);
        s_base=b0;
    }
    __syncthreads();
    int base=s_base;
    for(int t=c;t<TR*WIN;t+=256){
        int row=t/WIN, g=t%WIN;
        int gi=base+g;
        float d=(float)(r0+row)*dstep;
        float u=d-(float)gi*cstep;
        float v=expf(-u*u*inv2w2);
        rbf[row][g]=(gi>=0 && gi<NGs)?v:0.0f;
    }
    __syncthreads();
    float acc[TR];
    float b1=fb1[c];
    #pragma unroll
    for(int t=0;t<TR;t++) acc[t]=b1;
    #pragma unroll
    for(int g=0;g<WIN;g++){
        int gi=base+g;
        gi=(gi<0)?0:((gi>NGs-1)?NGs-1:gi);
        float w=fw1[gi*Hdim+c];
        #pragma unroll
        for(int t=0;t<TR;t++) acc[t]=fmaf(rbf[t][g],w,acc[t]);
    }
    __half* G=g_Gh+layer*NGRID*Hdim;
    #pragma unroll
    for(int t=0;t<TR;t++) G[(r0+t)*Hdim+c]=__float2half(gelu_f(acc[t]));
}

// --------------------------- tensor-core GEMM: C = act(A@W + b) [+Res]
// A fp16 [M,256] row-major, W fp16 [256,256] row-major ([k][n]).
// 32x64 CTA tile, 256 threads (8 warps as 2m x 4n), warp tile 16x16.
// mma.m16n8k16 fp16->fp32; 16 k-chunks.
template<bool GELU,bool RES,bool LAYERED,int MROWS>
__global__ void __launch_bounds__(256) k_tgemm(const __half* __restrict__ A,
                       const __half* __restrict__ W16,
                       const float* __restrict__ bias,
                       const float* __restrict__ Res,
                       float* __restrict__ Cf, __half* __restrict__ Ch){
    __shared__ __align__(16) __half As[32][24];
    __shared__ __align__(16) __half Ws[16][72];
    if(LAYERED){
        int L=blockIdx.z;
        A   += (size_t)L*MROWS*Hdim;
        W16 += (size_t)L*Hdim*Hdim;
        bias+= (size_t)L*Hdim;
        Ch  += (size_t)L*MROWS*Hdim;
    }
    int m0=blockIdx.x*32, n0=blockIdx.y*64;
    int tid=threadIdx.x;
    int wid=tid>>5, lane=tid&31;
    int wm=wid&1, wn=wid>>1;

    float acc[2][4];
    #pragma unroll
    for(int nb=0;nb<2;nb++)
        #pragma unroll
        for(int q=0;q<4;q++) acc[nb][q]=0.f;

    // fragment smem addresses (constant across chunks)
    unsigned a_addr=smem_u32(&As[wm*16 + (lane&7) + ((lane>>3)&1)*8][((lane>>4)&1)*8]);
    unsigned b_addr=smem_u32(&Ws[(lane&7) + ((lane>>3)&1)*8][wn*16 + ((lane>>4)&1)*8]);

    int ar=tid>>3, ac=(tid&7)*2;      // A fill: 32x16 halfs, 2 per thread
    int wr=tid>>4, wc=(tid&15)*4;     // W fill: 16x64 halfs, 4 per thread

    for(int k0=0;k0<Hdim;k0+=16){
        *reinterpret_cast<unsigned*>(&As[ar][ac]) =
            *reinterpret_cast<const unsigned*>(&A[(size_t)(m0+ar)*Hdim + k0 + ac]);
        *reinterpret_cast<uint2*>(&Ws[wr][wc]) =
            *reinterpret_cast<const uint2*>(&W16[(size_t)(k0+wr)*Hdim + n0 + wc]);
        __syncthreads();
        unsigned a0,a1,a2,a3, b0,b1,b2,b3;
        ldsm_x4 (a0,a1,a2,a3,a_addr);
        ldsm_x4t(b0,b1,b2,b3,b_addr);
        hmma(acc[0],a0,a1,a2,a3,b0,b1);
        hmma(acc[1],a0,a1,a2,a3,b2,b3);
        __syncthreads();
    }

    int row0=m0 + wm*16 + (lane>>2);
    int row1=row0+8;
    #pragma unroll
    for(int nb=0;nb<2;nb++){
        int col=n0 + wn*16 + nb*8 + (lane&3)*2;
        float bz0=bias[col], bz1=bias[col+1];
        float x00=acc[nb][0]+bz0, x01=acc[nb][1]+bz1;
        float x10=acc[nb][2]+bz0, x11=acc[nb][3]+bz1;
        if(GELU){
            x00=gelu_f(x00); x01=gelu_f(x01);
            x10=gelu_f(x10); x11=gelu_f(x11);
        }
        if(RES){
            x00+=Res[(size_t)row0*Hdim+col]; x01+=Res[(size_t)row0*Hdim+col+1];
            x10+=Res[(size_t)row1*Hdim+col]; x11+=Res[(size_t)row1*Hdim+col+1];
            *reinterpret_cast<float2*>(&Cf[(size_t)row0*Hdim+col])=make_float2(x00,x01);
            *reinterpret_cast<float2*>(&Cf[(size_t)row1*Hdim+col])=make_float2(x10,x11);
            *reinterpret_cast<__half2*>(&g_hh[(size_t)row0*Hdim+col])=__floats2half2_rn(x00,x01);
            *reinterpret_cast<__half2*>(&g_hh[(size_t)row1*Hdim+col])=__floats2half2_rn(x10,x11);
        }else{
            *reinterpret_cast<__half2*>(&Ch[(size_t)row0*Hdim+col])=__floats2half2_rn(x00,x01);
            *reinterpret_cast<__half2*>(&Ch[(size_t)row1*Hdim+col])=__floats2half2_rn(x10,x11);
        }
    }
}

// ------------------- neighbor aggregation: smem table, quadratic interp,
// 1024 threads (32 warps), 8 slots x 1 atom, explicit 4-way gather pipeline.
__device__ __forceinline__ void agg_step(unsigned p, __half2 hv,
                                         const __half2* __restrict__ tab_s,
                                         int c, float& ax, float& ay){
    int r=(p>>10)&511;
    float f=(float)(p>>19)*(1.0f/4096.0f)-1.0f;
    const __half2* base=tab_s + r*128 + c;
    float2 m=__half22float2(base[-128]);
    float2 z=__half22float2(base[0]);
    float2 q=__half22float2(base[128]);
    float2 hf=__half22float2(hv);
    float bx=0.5f*(q.x-m.x),      by=0.5f*(q.y-m.y);
    float cx=0.5f*(q.x+m.x)-z.x,  cy=0.5f*(q.y+m.y)-z.y;
    float wx=fmaf(f,fmaf(f,cx,bx),z.x);
    float wy=fmaf(f,fmaf(f,cy,by),z.y);
    ax=fmaf(wx,hf.x,ax);
    ay=fmaf(wy,hf.y,ay);
}

__global__ void __launch_bounds__(1024,1) k_agg(const __half2* __restrict__ tab){
    extern __shared__ __half2 tab_s[];     // NGRID*128 half2 = 192 KB
    int tid=threadIdx.x;
    {
        const uint4* src=reinterpret_cast<const uint4*>(tab);
        uint4* dst=reinterpret_cast<uint4*>(tab_s);
        #pragma unroll
        for(int idx=tid;idx<(NGRID*Hdim*2)/16;idx+=1024) dst[idx]=src[idx];
    }
    __syncthreads();
    int s=tid>>7;          // slot 0..7, one atom each
    int c=tid&127;         // half2 channel
    const __half2* __restrict__ hh=reinterpret_cast<const __half2*>(g_hh);
    int i=blockIdx.x*8 + s;
    int total=g_cnt[i];
    const unsigned* __restrict__ lst=g_nbr+i*Natoms;
    float ax=0.f, ay=0.f;
    int n=0;
    for(; n+4<=total; n+=4){
        unsigned p0=__ldg(lst+n+0);
        unsigned p1=__ldg(lst+n+1);
        unsigned p2=__ldg(lst+n+2);
        unsigned p3=__ldg(lst+n+3);
        __half2 h0=__ldg(hh+(p0&1023)*128+c);
        __half2 h1=__ldg(hh+(p1&1023)*128+c);
        __half2 h2=__ldg(hh+(p2&1023)*128+c);
        __half2 h3=__ldg(hh+(p3&1023)*128+c);
        agg_step(p0,h0,tab_s,c,ax,ay);
        agg_step(p1,h1,tab_s,c,ax,ay);
        agg_step(p2,h2,tab_s,c,ax,ay);
        agg_step(p3,h3,tab_s,c,ax,ay);
    }
    for(; n<total; n++){
        unsigned p=__ldg(lst+n);
        __half2 hv=__ldg(hh+(p&1023)*128+c);
        agg_step(p,hv,tab_s,c,ax,ay);
    }
    reinterpret_cast<__half2*>(g_aggh)[i*128+c]=__floats2half2_rn(ax,ay);
}

// ---------------------------------------------------------------- pooling
__global__ void k_pool(const int* __restrict__ batch){
    int b=blockIdx.x, c=threadIdx.x;
    float s=0.f;
    #pragma unroll 8
    for(int i=0;i<Natoms;i++){
        s += (batch[i]==b) ? g_h[i*Hdim+c] : 0.f;
    }
    g_pool[b*Hdim+c]=s;
}

// ------------------------------------------------- projection head + layernorm
__global__ void k_head(const float* __restrict__ pw1,const float* __restrict__ pb1,
                       const float* __restrict__ pw2,const float* __restrict__ pb2,
                       const float* __restrict__ lng,const float* __restrict__ lnb,
                       float* __restrict__ out){
    __shared__ float pv[Hdim];
    __shared__ float tv[Hdim];
    __shared__ float xv[Ldim];
    __shared__ float red[8];
    __shared__ float s_mu, s_inv;
    int b=blockIdx.x, tid=threadIdx.x;
    pv[tid]=g_pool[b*Hdim+tid];
    __syncthreads();
    float a=pb1[tid];
    for(int k=0;k<Hdim;k++) a=fmaf(pv[k],pw1[k*Hdim+tid],a);
    tv[tid]=gelu_f(a);
    __syncthreads();
    for(int o=tid;o<Ldim;o+=256){
        float x=pb2[o];
        for(int k=0;k<Hdim;k++) x=fmaf(tv[k],pw2[k*Ldim+o],x);
        xv[o]=x;
    }
    __syncthreads();
    float s=xv[tid]+xv[tid+256];
    for(int d=16;d>0;d>>=1) s+=__shfl_down_sync(0xffffffffu,s,d);
    if((tid&31)==0) red[tid>>5]=s;
    __syncthreads();
    if(tid==0){
        float t=0.f; for(int w=0;w<8;w++) t+=red[w];
        s_mu=t/(float)Ldim;
    }
    __syncthreads();
    float mu=s_mu;
    float d0=xv[tid]-mu, d1=xv[tid+256]-mu;
    float s2=d0*d0+d1*d1;
    for(int d=16;d>0;d>>=1) s2+=__shfl_down_sync(0xffffffffu,s2,d);
    if((tid&31)==0) red[tid>>5]=s2;
    __syncthreads();
    if(tid==0){
        float t=0.f; for(int w=0;w<8;w++) t+=red[w];
        s_inv=1.0f/sqrtf(t/(float)Ldim + 1e-5f);
    }
    __syncthreads();
    float inv=s_inv;
    out[b*Ldim+tid]     =(xv[tid]-mu)*inv*lng[tid]+lnb[tid];
    out[b*Ldim+tid+256] =(xv[tid+256]-mu)*inv*lng[tid+256]+lnb[tid+256];
}

// ------------------------------------------------------------------ launcher
extern "C" void kernel_launch(void* const* d_in, const int* in_sizes, int n_in,
                              void* d_out, int out_size){
    const int*   z    =(const int*)  d_in[0];
    const float* pos  =(const float*)d_in[1];
    const int*   batch=(const int*)  d_in[2];
    const float* emb  =(const float*)d_in[3];
    const float* fw1  =(const float*)d_in[4];
    const float* fb1  =(const float*)d_in[5];
    const float* fw2  =(const float*)d_in[6];
    const float* fb2  =(const float*)d_in[7];
    const float* aw1  =(const float*)d_in[8];
    const float* ab1  =(const float*)d_in[9];
    const float* aw2  =(const float*)d_in[10];
    const float* ab2  =(const float*)d_in[11];
    const float* pw1  =(const float*)d_in[12];
    const float* pb1  =(const float*)d_in[13];
    const float* pw2  =(const float*)d_in[14];
    const float* pb2  =(const float*)d_in[15];
    const float* lng  =(const float*)d_in[16];
    const float* lnb  =(const float*)d_in[17];
    float* out=(float*)d_out;

    float *ph;
    __half *ptab,*pGh,*paggh,*ptmph,*pfw2h,*paw1h,*paw2h;
    cudaGetSymbolAddress((void**)&ph,   g_h);
    cudaGetSymbolAddress((void**)&ptab, g_tab);
    cudaGetSymbolAddress((void**)&pGh,  g_Gh);
    cudaGetSymbolAddress((void**)&paggh,g_aggh);
    cudaGetSymbolAddress((void**)&ptmph,g_tmph);
    cudaGetSymbolAddress((void**)&pfw2h,g_fw2h);
    cudaGetSymbolAddress((void**)&paw1h,g_aw1h);
    cudaGetSymbolAddress((void**)&paw2h,g_aw2h);

    const int TAB_SMEM = NGRID*Hdim*2;   // 196608 B
    cudaFuncSetAttribute(k_agg, cudaFuncAttributeMaxDynamicSharedMemorySize, TAB_SMEM);

    k_embed<<<Natoms,Hdim>>>(z,emb);
    k_cvt<<<NIs*Hdim*Hdim/1024,1024>>>(fw2,aw1,aw2);
    k_nbr<<<Natoms,256>>>(pos);
    // build all 3 layers' filter tables upfront
    k_hidden<<<dim3(NGRID/TR,NIs),Hdim>>>(fw1,fb1);
    k_tgemm<false,false,true ,NGRID><<<dim3(NGRID/32,Hdim/64,NIs),256>>>(pGh, pfw2h, fb2, nullptr, nullptr, ptab);
    for(int l=0;l<NIs;l++){
        k_agg<<<Natoms/8,1024,TAB_SMEM>>>(reinterpret_cast<const __half2*>(ptab)+(size_t)l*NGRID*Hdim/2);
        k_tgemm<true ,false,false,Natoms><<<dim3(Natoms/32,Hdim/64),256>>>(paggh, paw1h+(size_t)l*Hdim*Hdim, ab1+l*Hdim, nullptr, nullptr, ptmph);
        k_tgemm<false,true ,false,Natoms><<<dim3(Natoms/32,Hdim/64),256>>>(ptmph, paw2h+(size_t)l*Hdim*Hdim, ab2+l*Hdim, ph, ph, nullptr);
    }
    k_pool<<<Bmol,Hdim>>>(batch);
    k_head<<<Bmol,Hdim>>>(pw1,pb1,pw2,pb2,lng,lnb,out);
}

// round 7
// speedup vs baseline: 1.8825x; 1.1791x over previous
#include <cuda_runtime.h>
#include <cuda_fp16.h>
#include <math.h>

#define Natoms 1024
#define Hdim   256
#define Ldim   512
#define NGs    50
#define NIs    3
#define Bmol   16
#define NGRID  384
#define CUT    5.0f
#define TR     16
#define WIN    11

typedef unsigned long long ull;

// scratch (no allocations allowed)
__device__ float  g_h[Natoms*Hdim];
__device__ __align__(16) __half g_hh[Natoms*Hdim];      // fp16 mirror of h
__device__ __align__(16) __half g_aggh[Natoms*Hdim];    // fp16 aggregation out
__device__ __align__(16) __half g_tmph[Natoms*Hdim];    // fp16 gemm1 out
__device__ __align__(16) __half g_Gh[NIs*NGRID*Hdim];   // fp16 gelu hidden of table MLP
__device__ __align__(16) __half g_tab[NIs*NGRID*Hdim];  // fp16 filter tables
__device__ __align__(16) __half g_fw2h[NIs*Hdim*Hdim];
__device__ __align__(16) __half g_aw1h[NIs*Hdim*Hdim];
__device__ __align__(16) __half g_aw2h[NIs*Hdim*Hdim];
__device__ float  g_pool[Bmol*Hdim];
__device__ unsigned g_nbr[Natoms*Natoms];               // packed neighbor list
__device__ int      g_cnt[Natoms];

__device__ __forceinline__ float gelu_f(float x){
    return 0.5f*x*(1.0f+erff(x*0.70710678118654752f));
}
__device__ __forceinline__ unsigned smem_u32(const void* p){
    return (unsigned)__cvta_generic_to_shared(p);
}
__device__ __forceinline__ void ldsm_x4(unsigned& r0,unsigned& r1,unsigned& r2,unsigned& r3,unsigned addr){
    asm volatile("ldmatrix.sync.aligned.m8n8.x4.shared.b16 {%0,%1,%2,%3}, [%4];"
        : "=r"(r0),"=r"(r1),"=r"(r2),"=r"(r3) : "r"(addr));
}
__device__ __forceinline__ void ldsm_x4t(unsigned& r0,unsigned& r1,unsigned& r2,unsigned& r3,unsigned addr){
    asm volatile("ldmatrix.sync.aligned.m8n8.x4.trans.shared.b16 {%0,%1,%2,%3}, [%4];"
        : "=r"(r0),"=r"(r1),"=r"(r2),"=r"(r3) : "r"(addr));
}
__device__ __forceinline__ void hmma(float* c, unsigned a0,unsigned a1,unsigned a2,unsigned a3,
                                     unsigned b0,unsigned b1){
    asm volatile("mma.sync.aligned.m16n8k16.row.col.f32.f16.f16.f32 "
        "{%0,%1,%2,%3}, {%4,%5,%6,%7}, {%8,%9}, {%0,%1,%2,%3};"
        : "+f"(c[0]),"+f"(c[1]),"+f"(c[2]),"+f"(c[3])
        : "r"(a0),"r"(a1),"r"(a2),"r"(a3),"r"(b0),"r"(b1));
}

// ---------------- prep: embedding + fp16 weight conversion + pool zero
__global__ void k_prep(const int* __restrict__ z, const float* __restrict__ emb,
                       const float* __restrict__ fw2, const float* __restrict__ aw1,
                       const float* __restrict__ aw2){
    int b=blockIdx.x, tid=threadIdx.x;
    if(b<Natoms){
        float v=emb[z[b]*Hdim+tid];
        g_h[b*Hdim+tid]=v;
        g_hh[b*Hdim+tid]=__float2half(v);
    }else if(b<Natoms+768){
        int idx=(b-Natoms)*256+tid;           // 768*256 = 196608 = NIs*Hdim*Hdim
        g_fw2h[idx]=__float2half(fw2[idx]);
        g_aw1h[idx]=__float2half(aw1[idx]);
        g_aw2h[idx]=__float2half(aw2[idx]);
    }else{
        int idx=(b-Natoms-768)*256+tid;       // 16*256 = 4096
        g_pool[idx]=0.f;
    }
}

// ------------------------------------------------ neighbor list (built once)
// packed: j(10) | r(9)<<10 | fq(13)<<19 ; r = round(t) clamped [1,NGRID-2], f=t-r in [-0.5,0.5]
__global__ void k_nbr(const float* __restrict__ pos){
    __shared__ int warp_cnt[8];
    int i=blockIdx.x, tid=threadIdx.x;
    float xi=pos[i*3+0], yi=pos[i*3+1], zi=pos[i*3+2];
    const float scale=(float)(NGRID-1)/CUT;
    int total=0;
    for(int base=0;base<Natoms;base+=256){
        int j=base+tid;
        float dx=pos[j*3+0]-xi;
        float dy=pos[j*3+1]-yi;
        float dz=pos[j*3+2]-zi;
        float d=sqrtf(dx*dx+dy*dy+dz*dz);
        bool keep=(j!=i)&&(d<CUT)&&(d>1e-6f);
        unsigned m=__ballot_sync(0xffffffffu,keep);
        if((tid&31)==0) warp_cnt[tid>>5]=__popc(m);
        __syncthreads();
        int off=total;
        int w=tid>>5;
        for(int ww=0;ww<w;ww++) off+=warp_cnt[ww];
        if(keep){
            int p=off+__popc(m&((1u<<(tid&31))-1u));
            float t=d*scale;
            int r=(int)(t+0.5f);
            if(r<1)r=1; if(r>NGRID-2)r=NGRID-2;
            float f=t-(float)r;
            int fq=(int)((f+1.0f)*4096.0f);
            if(fq<0)fq=0; if(fq>8191)fq=8191;
            g_nbr[i*Natoms+p]=(unsigned)j | ((unsigned)r<<10) | ((unsigned)fq<<19);
        }
        int bt=0;
        #pragma unroll
        for(int ww=0;ww<8;ww++) bt+=warp_cnt[ww];
        total+=bt;
        __syncthreads();
    }
    if(tid==0) g_cnt[i]=total;
}

// --------------------------------- table hidden: G = gelu(rbf @ fw1 + fb1), fp16 out
__global__ void k_hidden(const float* __restrict__ fw1all, const float* __restrict__ fb1all){
    __shared__ float rbf[TR][WIN+1];
    __shared__ int s_base;
    int layer=blockIdx.y;
    const float* fw1=fw1all+layer*NGs*Hdim;
    const float* fb1=fb1all+layer*Hdim;
    int r0=blockIdx.x*TR, c=threadIdx.x;
    const float dstep  = CUT/(float)(NGRID-1);
    const float cstep  = CUT/(float)(NGs-1);
    const float inv2w2 = 1.0f/(2.0f*0.05f*0.05f);

    if(c==0){
        float dmid=((float)r0+7.5f)*dstep;
        int b0=(int)(dmid/cstep+0.5f)-(WIN/2);
        s_base=b0;
    }
    __syncthreads();
    int base=s_base;
    for(int t=c;t<TR*WIN;t+=256){
        int row=t/WIN, g=t%WIN;
        int gi=base+g;
        float d=(float)(r0+row)*dstep;
        float u=d-(float)gi*cstep;
        float v=expf(-u*u*inv2w2);
        rbf[row][g]=(gi>=0 && gi<NGs)?v:0.0f;
    }
    __syncthreads();
    float acc[TR];
    float b1=fb1[c];
    #pragma unroll
    for(int t=0;t<TR;t++) acc[t]=b1;
    #pragma unroll
    for(int g=0;g<WIN;g++){
        int gi=base+g;
        gi=(gi<0)?0:((gi>NGs-1)?NGs-1:gi);
        float w=fw1[gi*Hdim+c];
        #pragma unroll
        for(int t=0;t<TR;t++) acc[t]=fmaf(rbf[t][g],w,acc[t]);
    }
    __half* G=g_Gh+layer*NGRID*Hdim;
    #pragma unroll
    for(int t=0;t<TR;t++) G[(r0+t)*Hdim+c]=__float2half(gelu_f(acc[t]));
}

// --------------------------- tensor-core GEMM: C = act(A@W + b) [+Res] [+pool]
template<bool GELU,bool RES,bool LAYERED,bool POOL,int MROWS>
__global__ void __launch_bounds__(256) k_tgemm(const __half* __restrict__ A,
                       const __half* __restrict__ W16,
                       const float* __restrict__ bias,
                       const float* __restrict__ Res,
                       float* __restrict__ Cf, __half* __restrict__ Ch,
                       const int* __restrict__ batch){
    __shared__ __align__(16) __half As[32][24];
    __shared__ __align__(16) __half Ws[16][72];
    if(LAYERED){
        int L=blockIdx.z;
        A   += (size_t)L*MROWS*Hdim;
        W16 += (size_t)L*Hdim*Hdim;
        bias+= (size_t)L*Hdim;
        Ch  += (size_t)L*MROWS*Hdim;
    }
    int m0=blockIdx.x*32, n0=blockIdx.y*64;
    int tid=threadIdx.x;
    int wid=tid>>5, lane=tid&31;
    int wm=wid&1, wn=wid>>1;

    float acc[2][4];
    #pragma unroll
    for(int nb=0;nb<2;nb++)
        #pragma unroll
        for(int q=0;q<4;q++) acc[nb][q]=0.f;

    unsigned a_addr=smem_u32(&As[wm*16 + (lane&7) + ((lane>>3)&1)*8][((lane>>4)&1)*8]);
    unsigned b_addr=smem_u32(&Ws[(lane&7) + ((lane>>3)&1)*8][wn*16 + ((lane>>4)&1)*8]);

    int ar=tid>>3, ac=(tid&7)*2;
    int wr=tid>>4, wc=(tid&15)*4;

    for(int k0=0;k0<Hdim;k0+=16){
        *reinterpret_cast<unsigned*>(&As[ar][ac]) =
            *reinterpret_cast<const unsigned*>(&A[(size_t)(m0+ar)*Hdim + k0 + ac]);
        *reinterpret_cast<uint2*>(&Ws[wr][wc]) =
            *reinterpret_cast<const uint2*>(&W16[(size_t)(k0+wr)*Hdim + n0 + wc]);
        __syncthreads();
        unsigned a0,a1,a2,a3, b0,b1,b2,b3;
        ldsm_x4 (a0,a1,a2,a3,a_addr);
        ldsm_x4t(b0,b1,b2,b3,b_addr);
        hmma(acc[0],a0,a1,a2,a3,b0,b1);
        hmma(acc[1],a0,a1,a2,a3,b2,b3);
        __syncthreads();
    }

    int row0=m0 + wm*16 + (lane>>2);
    int row1=row0+8;
    #pragma unroll
    for(int nb=0;nb<2;nb++){
        int col=n0 + wn*16 + nb*8 + (lane&3)*2;
        float bz0=bias[col], bz1=bias[col+1];
        float x00=acc[nb][0]+bz0, x01=acc[nb][1]+bz1;
        float x10=acc[nb][2]+bz0, x11=acc[nb][3]+bz1;
        if(GELU){
            x00=gelu_f(x00); x01=gelu_f(x01);
            x10=gelu_f(x10); x11=gelu_f(x11);
        }
        if(RES){
            x00+=Res[(size_t)row0*Hdim+col]; x01+=Res[(size_t)row0*Hdim+col+1];
            x10+=Res[(size_t)row1*Hdim+col]; x11+=Res[(size_t)row1*Hdim+col+1];
            *reinterpret_cast<float2*>(&Cf[(size_t)row0*Hdim+col])=make_float2(x00,x01);
            *reinterpret_cast<float2*>(&Cf[(size_t)row1*Hdim+col])=make_float2(x10,x11);
            *reinterpret_cast<__half2*>(&g_hh[(size_t)row0*Hdim+col])=__floats2half2_rn(x00,x01);
            *reinterpret_cast<__half2*>(&g_hh[(size_t)row1*Hdim+col])=__floats2half2_rn(x10,x11);
            if(POOL){
                int b0r=batch[row0], b1r=batch[row1];
                atomicAdd(&g_pool[b0r*Hdim+col  ],x00);
                atomicAdd(&g_pool[b0r*Hdim+col+1],x01);
                atomicAdd(&g_pool[b1r*Hdim+col  ],x10);
                atomicAdd(&g_pool[b1r*Hdim+col+1],x11);
            }
        }else{
            *reinterpret_cast<__half2*>(&Ch[(size_t)row0*Hdim+col])=__floats2half2_rn(x00,x01);
            *reinterpret_cast<__half2*>(&Ch[(size_t)row1*Hdim+col])=__floats2half2_rn(x10,x11);
        }
    }
}

// ------------------- neighbor aggregation: smem table, quadratic interp in half2
// 1024 threads (32 warps), 8 slots x 1 atom, explicit 4-way gather pipeline.
__device__ __forceinline__ void agg_step(unsigned p, __half2 hv,
                                         const __half2* __restrict__ tab_s,
                                         int c, float& ax, float& ay){
    int r=(p>>10)&511;
    float f=(float)(p>>19)*(1.0f/4096.0f)-1.0f;
    float f2=f*f;
    __half2 al=__float2half2_rn(0.5f*(f2+f));      // coeff of q (r+1)
    __half2 be=__float2half2_rn(1.0f-f2);          // coeff of z (r)
    __half2 ga=__float2half2_rn(0.5f*(f2-f));      // coeff of m (r-1)
    const __half2* base=tab_s + r*128 + c;
    __half2 m=base[-128];
    __half2 z=base[0];
    __half2 q=base[128];
    __half2 w=__hfma2(al,q,__hfma2(be,z,__hmul2(ga,m)));
    float2 pf=__half22float2(__hmul2(w,hv));
    ax+=pf.x; ay+=pf.y;
}

__global__ void __launch_bounds__(1024,1) k_agg(const __half2* __restrict__ tab){
    extern __shared__ __half2 tab_s[];     // NGRID*128 half2 = 192 KB
    int tid=threadIdx.x;
    {
        const uint4* src=reinterpret_cast<const uint4*>(tab);
        uint4* dst=reinterpret_cast<uint4*>(tab_s);
        #pragma unroll
        for(int idx=tid;idx<(NGRID*Hdim*2)/16;idx+=1024) dst[idx]=src[idx];
    }
    __syncthreads();
    int s=tid>>7;          // slot 0..7, one atom each
    int c=tid&127;         // half2 channel
    const __half2* __restrict__ hh=reinterpret_cast<const __half2*>(g_hh);
    int i=blockIdx.x*8 + s;
    int total=g_cnt[i];
    const unsigned* __restrict__ lst=g_nbr+i*Natoms;
    float ax=0.f, ay=0.f;
    int n=0;
    for(; n+4<=total; n+=4){
        unsigned p0=__ldg(lst+n+0);
        unsigned p1=__ldg(lst+n+1);
        unsigned p2=__ldg(lst+n+2);
        unsigned p3=__ldg(lst+n+3);
        __half2 h0=__ldg(hh+(p0&1023)*128+c);
        __half2 h1=__ldg(hh+(p1&1023)*128+c);
        __half2 h2=__ldg(hh+(p2&1023)*128+c);
        __half2 h3=__ldg(hh+(p3&1023)*128+c);
        agg_step(p0,h0,tab_s,c,ax,ay);
        agg_step(p1,h1,tab_s,c,ax,ay);
        agg_step(p2,h2,tab_s,c,ax,ay);
        agg_step(p3,h3,tab_s,c,ax,ay);
    }
    for(; n<total; n++){
        unsigned p=__ldg(lst+n);
        __half2 hv=__ldg(hh+(p&1023)*128+c);
        agg_step(p,hv,tab_s,c,ax,ay);
    }
    reinterpret_cast<__half2*>(g_aggh)[i*128+c]=__floats2half2_rn(ax,ay);
}

// ------------------------------------------------- projection head + layernorm
__global__ void __launch_bounds__(512) k_head(
                       const float* __restrict__ pw1,const float* __restrict__ pb1,
                       const float* __restrict__ pw2,const float* __restrict__ pb2,
                       const float* __restrict__ lng,const float* __restrict__ lnb,
                       float* __restrict__ out){
    __shared__ float pv[Hdim];
    __shared__ float tv[Hdim];
    __shared__ float red[16];
    __shared__ float s_mu, s_inv;
    int b=blockIdx.x, tid=threadIdx.x;
    if(tid<Hdim) pv[tid]=g_pool[b*Hdim+tid];
    __syncthreads();
    if(tid<Hdim){
        float a=pb1[tid];
        for(int k=0;k<Hdim;k++) a=fmaf(pv[k],pw1[k*Hdim+tid],a);
        tv[tid]=gelu_f(a);
    }
    __syncthreads();
    float x=pb2[tid];
    for(int k=0;k<Hdim;k++) x=fmaf(tv[k],pw2[k*Ldim+tid],x);
    // mean over 512 lanes
    float sv=x;
    for(int d=16;d>0;d>>=1) sv+=__shfl_down_sync(0xffffffffu,sv,d);
    if((tid&31)==0) red[tid>>5]=sv;
    __syncthreads();
    if(tid==0){
        float t=0.f;
        #pragma unroll
        for(int w=0;w<16;w++) t+=red[w];
        s_mu=t/(float)Ldim;
    }
    __syncthreads();
    float mu=s_mu;
    float dv=x-mu;
    float s2=dv*dv;
    for(int d=16;d>0;d>>=1) s2+=__shfl_down_sync(0xffffffffu,s2,d);
    if((tid&31)==0) red[tid>>5]=s2;
    __syncthreads();
    if(tid==0){
        float t=0.f;
        #pragma unroll
        for(int w=0;w<16;w++) t+=red[w];
        s_inv=1.0f/sqrtf(t/(float)Ldim + 1e-5f);
    }
    __syncthreads();
    out[b*Ldim+tid]=(x-mu)*s_inv*lng[tid]+lnb[tid];
}

// ------------------------------------------------------------------ launcher
extern "C" void kernel_launch(void* const* d_in, const int* in_sizes, int n_in,
                              void* d_out, int out_size){
    const int*   z    =(const int*)  d_in[0];
    const float* pos  =(const float*)d_in[1];
    const int*   batch=(const int*)  d_in[2];
    const float* emb  =(const float*)d_in[3];
    const float* fw1  =(const float*)d_in[4];
    const float* fb1  =(const float*)d_in[5];
    const float* fw2  =(const float*)d_in[6];
    const float* fb2  =(const float*)d_in[7];
    const float* aw1  =(const float*)d_in[8];
    const float* ab1  =(const float*)d_in[9];
    const float* aw2  =(const float*)d_in[10];
    const float* ab2  =(const float*)d_in[11];
    const float* pw1  =(const float*)d_in[12];
    const float* pb1  =(const float*)d_in[13];
    const float* pw2  =(const float*)d_in[14];
    const float* pb2  =(const float*)d_in[15];
    const float* lng  =(const float*)d_in[16];
    const float* lnb  =(const float*)d_in[17];
    float* out=(float*)d_out;

    float *ph;
    __half *ptab,*pGh,*paggh,*ptmph,*pfw2h,*paw1h,*paw2h;
    cudaGetSymbolAddress((void**)&ph,   g_h);
    cudaGetSymbolAddress((void**)&ptab, g_tab);
    cudaGetSymbolAddress((void**)&pGh,  g_Gh);
    cudaGetSymbolAddress((void**)&paggh,g_aggh);
    cudaGetSymbolAddress((void**)&ptmph,g_tmph);
    cudaGetSymbolAddress((void**)&pfw2h,g_fw2h);
    cudaGetSymbolAddress((void**)&paw1h,g_aw1h);
    cudaGetSymbolAddress((void**)&paw2h,g_aw2h);

    const int TAB_SMEM = NGRID*Hdim*2;   // 196608 B
    cudaFuncSetAttribute(k_agg, cudaFuncAttributeMaxDynamicSharedMemorySize, TAB_SMEM);

    k_prep<<<Natoms+768+16,256>>>(z,emb,fw2,aw1,aw2);
    k_nbr<<<Natoms,256>>>(pos);
    k_hidden<<<dim3(NGRID/TR,NIs),Hdim>>>(fw1,fb1);
    k_tgemm<false,false,true ,false,NGRID><<<dim3(NGRID/32,Hdim/64,NIs),256>>>(pGh, pfw2h, fb2, nullptr, nullptr, ptab, nullptr);
    for(int l=0;l<NIs;l++){
        k_agg<<<Natoms/8,1024,TAB_SMEM>>>(reinterpret_cast<const __half2*>(ptab)+(size_t)l*NGRID*Hdim/2);
        k_tgemm<true ,false,false,false,Natoms><<<dim3(Natoms/32,Hdim/64),256>>>(paggh, paw1h+(size_t)l*Hdim*Hdim, ab1+l*Hdim, nullptr, nullptr, ptmph, nullptr);
        if(l<NIs-1)
            k_tgemm<false,true ,false,false,Natoms><<<dim3(Natoms/32,Hdim/64),256>>>(ptmph, paw2h+(size_t)l*Hdim*Hdim, ab2+l*Hdim, ph, ph, nullptr, nullptr);
        else
            k_tgemm<false,true ,false,true ,Natoms><<<dim3(Natoms/32,Hdim/64),256>>>(ptmph, paw2h+(size_t)l*Hdim*Hdim, ab2+l*Hdim, ph, ph, nullptr, batch);
    }
    k_head<<<Bmol,512>>>(pw1,pb1,pw2,pb2,lng,lnb,out);
}

// round 8
// speedup vs baseline: 1.9555x; 1.0388x over previous
#include <cuda_runtime.h>
#include <cuda_fp16.h>
#include <math.h>

#define Natoms 1024
#define Hdim   256
#define Ldim   512
#define NGs    50
#define NIs    3
#define Bmol   16
#define NGRID  384
#define CUT    5.0f
#define TR     16
#define WIN    11

#define A_PAD 264     // halfs per A smem row (16B/row bank shift)
#define W_PAD 72      // halfs per W smem row
#define GEMM_SMEM (32*A_PAD*2 + 256*W_PAD*2)   // 16896 + 36864 = 53760 B

typedef unsigned long long ull;

// scratch (no allocations allowed)
__device__ float  g_h[Natoms*Hdim];
__device__ __align__(16) __half g_hh[Natoms*Hdim];
__device__ __align__(16) __half g_aggh[Natoms*Hdim];
__device__ __align__(16) __half g_tmph[Natoms*Hdim];
__device__ __align__(16) __half g_Gh[NIs*NGRID*Hdim];
__device__ __align__(16) __half g_tab[NIs*NGRID*Hdim];
__device__ __align__(16) __half g_fw2h[NIs*Hdim*Hdim];
__device__ __align__(16) __half g_aw1h[NIs*Hdim*Hdim];
__device__ __align__(16) __half g_aw2h[NIs*Hdim*Hdim];
__device__ float  g_pool[Bmol*Hdim];
__device__ unsigned g_nbr[Natoms*Natoms];
__device__ int      g_cnt[Natoms];

__device__ __forceinline__ float gelu_f(float x){
    return 0.5f*x*(1.0f+erff(x*0.70710678118654752f));
}
__device__ __forceinline__ unsigned smem_u32(const void* p){
    return (unsigned)__cvta_generic_to_shared(p);
}
__device__ __forceinline__ void ldsm_x4(unsigned& r0,unsigned& r1,unsigned& r2,unsigned& r3,unsigned addr){
    asm volatile("ldmatrix.sync.aligned.m8n8.x4.shared.b16 {%0,%1,%2,%3}, [%4];"
        : "=r"(r0),"=r"(r1),"=r"(r2),"=r"(r3) : "r"(addr));
}
__device__ __forceinline__ void ldsm_x4t(unsigned& r0,unsigned& r1,unsigned& r2,unsigned& r3,unsigned addr){
    asm volatile("ldmatrix.sync.aligned.m8n8.x4.trans.shared.b16 {%0,%1,%2,%3}, [%4];"
        : "=r"(r0),"=r"(r1),"=r"(r2),"=r"(r3) : "r"(addr));
}
__device__ __forceinline__ void hmma(float* c, unsigned a0,unsigned a1,unsigned a2,unsigned a3,
                                     unsigned b0,unsigned b1){
    asm volatile("mma.sync.aligned.m16n8k16.row.col.f32.f16.f16.f32 "
        "{%0,%1,%2,%3}, {%4,%5,%6,%7}, {%8,%9}, {%0,%1,%2,%3};"
        : "+f"(c[0]),"+f"(c[1]),"+f"(c[2]),"+f"(c[3])
        : "r"(a0),"r"(a1),"r"(a2),"r"(a3),"r"(b0),"r"(b1));
}

// ---------------- prep: embedding + fp16 weight conversion + pool zero
__global__ void k_prep(const int* __restrict__ z, const float* __restrict__ emb,
                       const float* __restrict__ fw2, const float* __restrict__ aw1,
                       const float* __restrict__ aw2){
    int b=blockIdx.x, tid=threadIdx.x;
    if(b<Natoms){
        float v=emb[z[b]*Hdim+tid];
        g_h[b*Hdim+tid]=v;
        g_hh[b*Hdim+tid]=__float2half(v);
    }else if(b<Natoms+768){
        int idx=(b-Natoms)*256+tid;
        g_fw2h[idx]=__float2half(fw2[idx]);
        g_aw1h[idx]=__float2half(aw1[idx]);
        g_aw2h[idx]=__float2half(aw2[idx]);
    }else{
        int idx=(b-Natoms-768)*256+tid;
        g_pool[idx]=0.f;
    }
}

// ------------------------------------------------ neighbor list (built once)
__global__ void k_nbr(const float* __restrict__ pos){
    __shared__ int warp_cnt[8];
    int i=blockIdx.x, tid=threadIdx.x;
    float xi=pos[i*3+0], yi=pos[i*3+1], zi=pos[i*3+2];
    const float scale=(float)(NGRID-1)/CUT;
    int total=0;
    for(int base=0;base<Natoms;base+=256){
        int j=base+tid;
        float dx=pos[j*3+0]-xi;
        float dy=pos[j*3+1]-yi;
        float dz=pos[j*3+2]-zi;
        float d=sqrtf(dx*dx+dy*dy+dz*dz);
        bool keep=(j!=i)&&(d<CUT)&&(d>1e-6f);
        unsigned m=__ballot_sync(0xffffffffu,keep);
        if((tid&31)==0) warp_cnt[tid>>5]=__popc(m);
        __syncthreads();
        int off=total;
        int w=tid>>5;
        for(int ww=0;ww<w;ww++) off+=warp_cnt[ww];
        if(keep){
            int p=off+__popc(m&((1u<<(tid&31))-1u));
            float t=d*scale;
            int r=(int)(t+0.5f);
            if(r<1)r=1; if(r>NGRID-2)r=NGRID-2;
            float f=t-(float)r;
            int fq=(int)((f+1.0f)*4096.0f);
            if(fq<0)fq=0; if(fq>8191)fq=8191;
            g_nbr[i*Natoms+p]=(unsigned)j | ((unsigned)r<<10) | ((unsigned)fq<<19);
        }
        int bt=0;
        #pragma unroll
        for(int ww=0;ww<8;ww++) bt+=warp_cnt[ww];
        total+=bt;
        __syncthreads();
    }
    if(tid==0) g_cnt[i]=total;
}

// --------------------------------- table hidden: G = gelu(rbf @ fw1 + fb1), fp16 out
__global__ void k_hidden(const float* __restrict__ fw1all, const float* __restrict__ fb1all){
    __shared__ float rbf[TR][WIN+1];
    __shared__ int s_base;
    int layer=blockIdx.y;
    const float* fw1=fw1all+layer*NGs*Hdim;
    const float* fb1=fb1all+layer*Hdim;
    int r0=blockIdx.x*TR, c=threadIdx.x;
    const float dstep  = CUT/(float)(NGRID-1);
    const float cstep  = CUT/(float)(NGs-1);
    const float inv2w2 = 1.0f/(2.0f*0.05f*0.05f);

    if(c==0){
        float dmid=((float)r0+7.5f)*dstep;
        int b0=(int)(dmid/cstep+0.5f)-(WIN/2);
        s_base=b0;
    }
    __syncthreads();
    int base=s_base;
    for(int t=c;t<TR*WIN;t+=256){
        int row=t/WIN, g=t%WIN;
        int gi=base+g;
        float d=(float)(r0+row)*dstep;
        float u=d-(float)gi*cstep;
        float v=expf(-u*u*inv2w2);
        rbf[row][g]=(gi>=0 && gi<NGs)?v:0.0f;
    }
    __syncthreads();
    float acc[TR];
    float b1=fb1[c];
    #pragma unroll
    for(int t=0;t<TR;t++) acc[t]=b1;
    #pragma unroll
    for(int g=0;g<WIN;g++){
        int gi=base+g;
        gi=(gi<0)?0:((gi>NGs-1)?NGs-1:gi);
        float w=fw1[gi*Hdim+c];
        #pragma unroll
        for(int t=0;t<TR;t++) acc[t]=fmaf(rbf[t][g],w,acc[t]);
    }
    __half* G=g_Gh+layer*NGRID*Hdim;
    #pragma unroll
    for(int t=0;t<TR;t++) G[(r0+t)*Hdim+c]=__float2half(gelu_f(acc[t]));
}

// --------------------------- tensor-core GEMM: C = act(A@W + b) [+Res] [+pool]
// Full-K smem resident: A 32x256 + W 256x64, ONE barrier, 16 unrolled chunks.
template<bool GELU,bool RES,bool LAYERED,bool POOL,int MROWS>
__global__ void __launch_bounds__(256) k_tgemm(const __half* __restrict__ A,
                       const __half* __restrict__ W16,
                       const float* __restrict__ bias,
                       const float* __restrict__ Res,
                       float* __restrict__ Cf, __half* __restrict__ Ch,
                       const int* __restrict__ batch){
    extern __shared__ __align__(16) __half sm[];
    __half* As=sm;                       // [32][A_PAD]
    __half* Ws=sm+32*A_PAD;              // [256][W_PAD]
    if(LAYERED){
        int L=blockIdx.z;
        A   += (size_t)L*MROWS*Hdim;
        W16 += (size_t)L*Hdim*Hdim;
        bias+= (size_t)L*Hdim;
        Ch  += (size_t)L*MROWS*Hdim;
    }
    int m0=blockIdx.x*32, n0=blockIdx.y*64;
    int tid=threadIdx.x;
    int wid=tid>>5, lane=tid&31;
    int wm=wid&1, wn=wid>>1;

    // bulk fill: A 32x256 (4 uint4/thread), W 256x64 (8 uint4/thread = 1 row)
    {
        int ar=tid>>3, ac=(tid&7)*8;
        #pragma unroll
        for(int p=0;p<4;p++){
            *reinterpret_cast<uint4*>(&As[ar*A_PAD + p*64 + ac]) =
                *reinterpret_cast<const uint4*>(&A[(size_t)(m0+ar)*Hdim + p*64 + ac]);
        }
        const __half* wrow=&W16[(size_t)tid*Hdim + n0];
        __half* srow=&Ws[tid*W_PAD];
        #pragma unroll
        for(int c=0;c<8;c++){
            *reinterpret_cast<uint4*>(&srow[c*8]) =
                *reinterpret_cast<const uint4*>(&wrow[c*8]);
        }
    }
    __syncthreads();

    float acc[2][4];
    #pragma unroll
    for(int nb=0;nb<2;nb++)
        #pragma unroll
        for(int q=0;q<4;q++) acc[nb][q]=0.f;

    unsigned a_base=smem_u32(&As[(wm*16 + (lane&7) + ((lane>>3)&1)*8)*A_PAD + ((lane>>4)&1)*8]);
    unsigned b_base=smem_u32(&Ws[((lane&7) + ((lane>>3)&1)*8)*W_PAD + wn*16 + ((lane>>4)&1)*8]);

    #pragma unroll
    for(int kc=0;kc<16;kc++){
        unsigned a0,a1,a2,a3, b0,b1,b2,b3;
        ldsm_x4 (a0,a1,a2,a3, a_base + kc*16*2);
        ldsm_x4t(b0,b1,b2,b3, b_base + kc*16*W_PAD*2);
        hmma(acc[0],a0,a1,a2,a3,b0,b1);
        hmma(acc[1],a0,a1,a2,a3,b2,b3);
    }

    int row0=m0 + wm*16 + (lane>>2);
    int row1=row0+8;
    #pragma unroll
    for(int nb=0;nb<2;nb++){
        int col=n0 + wn*16 + nb*8 + (lane&3)*2;
        float bz0=bias[col], bz1=bias[col+1];
        float x00=acc[nb][0]+bz0, x01=acc[nb][1]+bz1;
        float x10=acc[nb][2]+bz0, x11=acc[nb][3]+bz1;
        if(GELU){
            x00=gelu_f(x00); x01=gelu_f(x01);
            x10=gelu_f(x10); x11=gelu_f(x11);
        }
        if(RES){
            x00+=Res[(size_t)row0*Hdim+col]; x01+=Res[(size_t)row0*Hdim+col+1];
            x10+=Res[(size_t)row1*Hdim+col]; x11+=Res[(size_t)row1*Hdim+col+1];
            *reinterpret_cast<float2*>(&Cf[(size_t)row0*Hdim+col])=make_float2(x00,x01);
            *reinterpret_cast<float2*>(&Cf[(size_t)row1*Hdim+col])=make_float2(x10,x11);
            *reinterpret_cast<__half2*>(&g_hh[(size_t)row0*Hdim+col])=__floats2half2_rn(x00,x01);
            *reinterpret_cast<__half2*>(&g_hh[(size_t)row1*Hdim+col])=__floats2half2_rn(x10,x11);
            if(POOL){
                int b0r=batch[row0], b1r=batch[row1];
                atomicAdd(&g_pool[b0r*Hdim+col  ],x00);
                atomicAdd(&g_pool[b0r*Hdim+col+1],x01);
                atomicAdd(&g_pool[b1r*Hdim+col  ],x10);
                atomicAdd(&g_pool[b1r*Hdim+col+1],x11);
            }
        }else{
            *reinterpret_cast<__half2*>(&Ch[(size_t)row0*Hdim+col])=__floats2half2_rn(x00,x01);
            *reinterpret_cast<__half2*>(&Ch[(size_t)row1*Hdim+col])=__floats2half2_rn(x10,x11);
        }
    }
}

// ------------------- neighbor aggregation: smem table, quadratic interp in half2
__device__ __forceinline__ void agg_step(unsigned p, __half2 hv,
                                         const __half2* __restrict__ tab_s,
                                         int c, float& ax, float& ay){
    int r=(p>>10)&511;
    float f=(float)(p>>19)*(1.0f/4096.0f)-1.0f;
    float f2=f*f;
    __half2 al=__float2half2_rn(0.5f*(f2+f));
    __half2 be=__float2half2_rn(1.0f-f2);
    __half2 ga=__float2half2_rn(0.5f*(f2-f));
    const __half2* base=tab_s + r*128 + c;
    __half2 m=base[-128];
    __half2 z=base[0];
    __half2 q=base[128];
    __half2 w=__hfma2(al,q,__hfma2(be,z,__hmul2(ga,m)));
    float2 pf=__half22float2(__hmul2(w,hv));
    ax+=pf.x; ay+=pf.y;
}

__global__ void __launch_bounds__(1024,1) k_agg(const __half2* __restrict__ tab){
    extern __shared__ __half2 tab_s[];
    int tid=threadIdx.x;
    {
        const uint4* src=reinterpret_cast<const uint4*>(tab);
        uint4* dst=reinterpret_cast<uint4*>(tab_s);
        #pragma unroll
        for(int idx=tid;idx<(NGRID*Hdim*2)/16;idx+=1024) dst[idx]=src[idx];
    }
    __syncthreads();
    int s=tid>>7;
    int c=tid&127;
    const __half2* __restrict__ hh=reinterpret_cast<const __half2*>(g_hh);
    int i=blockIdx.x*8 + s;
    int total=g_cnt[i];
    const unsigned* __restrict__ lst=g_nbr+i*Natoms;
    float ax=0.f, ay=0.f;
    int n=0;
    for(; n+4<=total; n+=4){
        unsigned p0=__ldg(lst+n+0);
        unsigned p1=__ldg(lst+n+1);
        unsigned p2=__ldg(lst+n+2);
        unsigned p3=__ldg(lst+n+3);
        __half2 h0=__ldg(hh+(p0&1023)*128+c);
        __half2 h1=__ldg(hh+(p1&1023)*128+c);
        __half2 h2=__ldg(hh+(p2&1023)*128+c);
        __half2 h3=__ldg(hh+(p3&1023)*128+c);
        agg_step(p0,h0,tab_s,c,ax,ay);
        agg_step(p1,h1,tab_s,c,ax,ay);
        agg_step(p2,h2,tab_s,c,ax,ay);
        agg_step(p3,h3,tab_s,c,ax,ay);
    }
    for(; n<total; n++){
        unsigned p=__ldg(lst+n);
        __half2 hv=__ldg(hh+(p&1023)*128+c);
        agg_step(p,hv,tab_s,c,ax,ay);
    }
    reinterpret_cast<__half2*>(g_aggh)[i*128+c]=__floats2half2_rn(ax,ay);
}

// ------------------------------------------------- projection head + layernorm
__global__ void __launch_bounds__(512) k_head(
                       const float* __restrict__ pw1,const float* __restrict__ pb1,
                       const float* __restrict__ pw2,const float* __restrict__ pb2,
                       const float* __restrict__ lng,const float* __restrict__ lnb,
                       float* __restrict__ out){
    __shared__ float pv[Hdim];
    __shared__ float tv[Hdim];
    __shared__ float red[16];
    __shared__ float s_mu, s_inv;
    int b=blockIdx.x, tid=threadIdx.x;
    if(tid<Hdim) pv[tid]=g_pool[b*Hdim+tid];
    __syncthreads();
    if(tid<Hdim){
        float a=pb1[tid];
        for(int k=0;k<Hdim;k++) a=fmaf(pv[k],pw1[k*Hdim+tid],a);
        tv[tid]=gelu_f(a);
    }
    __syncthreads();
    float x=pb2[tid];
    for(int k=0;k<Hdim;k++) x=fmaf(tv[k],pw2[k*Ldim+tid],x);
    float sv=x;
    for(int d=16;d>0;d>>=1) sv+=__shfl_down_sync(0xffffffffu,sv,d);
    if((tid&31)==0) red[tid>>5]=sv;
    __syncthreads();
    if(tid==0){
        float t=0.f;
        #pragma unroll
        for(int w=0;w<16;w++) t+=red[w];
        s_mu=t/(float)Ldim;
    }
    __syncthreads();
    float mu=s_mu;
    float dv=x-mu;
    float s2=dv*dv;
    for(int d=16;d>0;d>>=1) s2+=__shfl_down_sync(0xffffffffu,s2,d);
    if((tid&31)==0) red[tid>>5]=s2;
    __syncthreads();
    if(tid==0){
        float t=0.f;
        #pragma unroll
        for(int w=0;w<16;w++) t+=red[w];
        s_inv=1.0f/sqrtf(t/(float)Ldim + 1e-5f);
    }
    __syncthreads();
    out[b*Ldim+tid]=(x-mu)*s_inv*lng[tid]+lnb[tid];
}

// ------------------------------------------------------------------ launcher
extern "C" void kernel_launch(void* const* d_in, const int* in_sizes, int n_in,
                              void* d_out, int out_size){
    const int*   z    =(const int*)  d_in[0];
    const float* pos  =(const float*)d_in[1];
    const int*   batch=(const int*)  d_in[2];
    const float* emb  =(const float*)d_in[3];
    const float* fw1  =(const float*)d_in[4];
    const float* fb1  =(const float*)d_in[5];
    const float* fw2  =(const float*)d_in[6];
    const float* fb2  =(const float*)d_in[7];
    const float* aw1  =(const float*)d_in[8];
    const float* ab1  =(const float*)d_in[9];
    const float* aw2  =(const float*)d_in[10];
    const float* ab2  =(const float*)d_in[11];
    const float* pw1  =(const float*)d_in[12];
    const float* pb1  =(const float*)d_in[13];
    const float* pw2  =(const float*)d_in[14];
    const float* pb2  =(const float*)d_in[15];
    const float* lng  =(const float*)d_in[16];
    const float* lnb  =(const float*)d_in[17];
    float* out=(float*)d_out;

    float *ph;
    __half *ptab,*pGh,*paggh,*ptmph,*pfw2h,*paw1h,*paw2h;
    cudaGetSymbolAddress((void**)&ph,   g_h);
    cudaGetSymbolAddress((void**)&ptab, g_tab);
    cudaGetSymbolAddress((void**)&pGh,  g_Gh);
    cudaGetSymbolAddress((void**)&paggh,g_aggh);
    cudaGetSymbolAddress((void**)&ptmph,g_tmph);
    cudaGetSymbolAddress((void**)&pfw2h,g_fw2h);
    cudaGetSymbolAddress((void**)&paw1h,g_aw1h);
    cudaGetSymbolAddress((void**)&paw2h,g_aw2h);

    const int TAB_SMEM = NGRID*Hdim*2;   // 196608 B
    cudaFuncSetAttribute(k_agg, cudaFuncAttributeMaxDynamicSharedMemorySize, TAB_SMEM);
    cudaFuncSetAttribute((const void*)k_tgemm<false,false,true ,false,NGRID>,
                         cudaFuncAttributeMaxDynamicSharedMemorySize, GEMM_SMEM);
    cudaFuncSetAttribute((const void*)k_tgemm<true ,false,false,false,Natoms>,
                         cudaFuncAttributeMaxDynamicSharedMemorySize, GEMM_SMEM);
    cudaFuncSetAttribute((const void*)k_tgemm<false,true ,false,false,Natoms>,
                         cudaFuncAttributeMaxDynamicSharedMemorySize, GEMM_SMEM);
    cudaFuncSetAttribute((const void*)k_tgemm<false,true ,false,true ,Natoms>,
                         cudaFuncAttributeMaxDynamicSharedMemorySize, GEMM_SMEM);

    k_prep<<<Natoms+768+16,256>>>(z,emb,fw2,aw1,aw2);
    k_nbr<<<Natoms,256>>>(pos);
    k_hidden<<<dim3(NGRID/TR,NIs),Hdim>>>(fw1,fb1);
    k_tgemm<false,false,true ,false,NGRID><<<dim3(NGRID/32,Hdim/64,NIs),256,GEMM_SMEM>>>(pGh, pfw2h, fb2, nullptr, nullptr, ptab, nullptr);
    for(int l=0;l<NIs;l++){
        k_agg<<<Natoms/8,1024,TAB_SMEM>>>(reinterpret_cast<const __half2*>(ptab)+(size_t)l*NGRID*Hdim/2);
        k_tgemm<true ,false,false,false,Natoms><<<dim3(Natoms/32,Hdim/64),256,GEMM_SMEM>>>(paggh, paw1h+(size_t)l*Hdim*Hdim, ab1+l*Hdim, nullptr, nullptr, ptmph, nullptr);
        if(l<NIs-1)
            k_tgemm<false,true ,false,false,Natoms><<<dim3(Natoms/32,Hdim/64),256,GEMM_SMEM>>>(ptmph, paw2h+(size_t)l*Hdim*Hdim, ab2+l*Hdim, ph, ph, nullptr, nullptr);
        else
            k_tgemm<false,true ,false,true ,Natoms><<<dim3(Natoms/32,Hdim/64),256,GEMM_SMEM>>>(ptmph, paw2h+(size_t)l*Hdim*Hdim, ab2+l*Hdim, ph, ph, nullptr, batch);
    }
    k_head<<<Bmol,512>>>(pw1,pb1,pw2,pb2,lng,lnb,out);
}

// round 9
// speedup vs baseline: 2.4317x; 1.2435x over previous
#include <cuda_runtime.h>
#include <cuda_fp16.h>
#include <math.h>

#define Natoms 1024
#define Hdim   256
#define Ldim   512
#define NGs    50
#define NIs    3
#define Bmol   16
#define NGRID  384
#define CUT    5.0f
#define TR     16
#define WIN    11

#define A_PAD 264
#define W_PAD 72
#define GEMM_SMEM (32*A_PAD*2 + 256*W_PAD*2)
#define AGG_SMEM (NGRID*Hdim*2 + 8*256*4)   // table + strip-reduction buffer

typedef unsigned long long ull;

// scratch (no allocations allowed)
__device__ float  g_h[Natoms*Hdim];
__device__ __align__(16) __half g_hh[Natoms*Hdim];
__device__ __align__(16) __half g_aggh[Natoms*Hdim];
__device__ __align__(16) __half g_tmph[Natoms*Hdim];
__device__ __align__(16) __half g_Gh[NIs*NGRID*Hdim];
__device__ __align__(16) __half g_tab[NIs*NGRID*Hdim];
__device__ __align__(16) __half g_fw2h[NIs*Hdim*Hdim];
__device__ __align__(16) __half g_aw1h[NIs*Hdim*Hdim];
__device__ __align__(16) __half g_aw2h[NIs*Hdim*Hdim];
__device__ float  g_pool[Bmol*Hdim];
__device__ unsigned g_nbr[Natoms*Natoms];
__device__ int      g_cnt[Natoms];

__device__ __forceinline__ float gelu_f(float x){
    return 0.5f*x*(1.0f+erff(x*0.70710678118654752f));
}
__device__ __forceinline__ unsigned smem_u32(const void* p){
    return (unsigned)__cvta_generic_to_shared(p);
}
__device__ __forceinline__ void ldsm_x4(unsigned& r0,unsigned& r1,unsigned& r2,unsigned& r3,unsigned addr){
    asm volatile("ldmatrix.sync.aligned.m8n8.x4.shared.b16 {%0,%1,%2,%3}, [%4];"
        : "=r"(r0),"=r"(r1),"=r"(r2),"=r"(r3) : "r"(addr));
}
__device__ __forceinline__ void ldsm_x4t(unsigned& r0,unsigned& r1,unsigned& r2,unsigned& r3,unsigned addr){
    asm volatile("ldmatrix.sync.aligned.m8n8.x4.trans.shared.b16 {%0,%1,%2,%3}, [%4];"
        : "=r"(r0),"=r"(r1),"=r"(r2),"=r"(r3) : "r"(addr));
}
__device__ __forceinline__ void hmma(float* c, unsigned a0,unsigned a1,unsigned a2,unsigned a3,
                                     unsigned b0,unsigned b1){
    asm volatile("mma.sync.aligned.m16n8k16.row.col.f32.f16.f16.f32 "
        "{%0,%1,%2,%3}, {%4,%5,%6,%7}, {%8,%9}, {%0,%1,%2,%3};"
        : "+f"(c[0]),"+f"(c[1]),"+f"(c[2]),"+f"(c[3])
        : "r"(a0),"r"(a1),"r"(a2),"r"(a3),"r"(b0),"r"(b1));
}

// ---------------- prep: embedding + fp16 weight conversion + pool zero
__global__ void k_prep(const int* __restrict__ z, const float* __restrict__ emb,
                       const float* __restrict__ fw2, const float* __restrict__ aw1,
                       const float* __restrict__ aw2){
    int b=blockIdx.x, tid=threadIdx.x;
    if(b<Natoms){
        float v=emb[z[b]*Hdim+tid];
        g_h[b*Hdim+tid]=v;
        g_hh[b*Hdim+tid]=__float2half(v);
    }else if(b<Natoms+768){
        int idx=(b-Natoms)*256+tid;
        g_fw2h[idx]=__float2half(fw2[idx]);
        g_aw1h[idx]=__float2half(aw1[idx]);
        g_aw2h[idx]=__float2half(aw2[idx]);
    }else{
        int idx=(b-Natoms-768)*256+tid;
        g_pool[idx]=0.f;
    }
}

// ------------------------------------------------ neighbor list (built once)
__global__ void k_nbr(const float* __restrict__ pos){
    __shared__ int warp_cnt[8];
    int i=blockIdx.x, tid=threadIdx.x;
    float xi=pos[i*3+0], yi=pos[i*3+1], zi=pos[i*3+2];
    const float scale=(float)(NGRID-1)/CUT;
    int total=0;
    for(int base=0;base<Natoms;base+=256){
        int j=base+tid;
        float dx=pos[j*3+0]-xi;
        float dy=pos[j*3+1]-yi;
        float dz=pos[j*3+2]-zi;
        float d=sqrtf(dx*dx+dy*dy+dz*dz);
        bool keep=(j!=i)&&(d<CUT)&&(d>1e-6f);
        unsigned m=__ballot_sync(0xffffffffu,keep);
        if((tid&31)==0) warp_cnt[tid>>5]=__popc(m);
        __syncthreads();
        int off=total;
        int w=tid>>5;
        for(int ww=0;ww<w;ww++) off+=warp_cnt[ww];
        if(keep){
            int p=off+__popc(m&((1u<<(tid&31))-1u));
            float t=d*scale;
            int r=(int)(t+0.5f);
            if(r<1)r=1; if(r>NGRID-2)r=NGRID-2;
            float f=t-(float)r;
            int fq=(int)((f+1.0f)*4096.0f);
            if(fq<0)fq=0; if(fq>8191)fq=8191;
            g_nbr[i*Natoms+p]=(unsigned)j | ((unsigned)r<<10) | ((unsigned)fq<<19);
        }
        int bt=0;
        #pragma unroll
        for(int ww=0;ww<8;ww++) bt+=warp_cnt[ww];
        total+=bt;
        __syncthreads();
    }
    if(tid==0) g_cnt[i]=total;
}

// --------------------------------- table hidden: G = gelu(rbf @ fw1 + fb1), fp16 out
__global__ void k_hidden(const float* __restrict__ fw1all, const float* __restrict__ fb1all){
    __shared__ float rbf[TR][WIN+1];
    __shared__ int s_base;
    int layer=blockIdx.y;
    const float* fw1=fw1all+layer*NGs*Hdim;
    const float* fb1=fb1all+layer*Hdim;
    int r0=blockIdx.x*TR, c=threadIdx.x;
    const float dstep  = CUT/(float)(NGRID-1);
    const float cstep  = CUT/(float)(NGs-1);
    const float inv2w2 = 1.0f/(2.0f*0.05f*0.05f);

    if(c==0){
        float dmid=((float)r0+7.5f)*dstep;
        int b0=(int)(dmid/cstep+0.5f)-(WIN/2);
        s_base=b0;
    }
    __syncthreads();
    int base=s_base;
    for(int t=c;t<TR*WIN;t+=256){
        int row=t/WIN, g=t%WIN;
        int gi=base+g;
        float d=(float)(r0+row)*dstep;
        float u=d-(float)gi*cstep;
        float v=expf(-u*u*inv2w2);
        rbf[row][g]=(gi>=0 && gi<NGs)?v:0.0f;
    }
    __syncthreads();
    float acc[TR];
    float b1=fb1[c];
    #pragma unroll
    for(int t=0;t<TR;t++) acc[t]=b1;
    #pragma unroll
    for(int g=0;g<WIN;g++){
        int gi=base+g;
        gi=(gi<0)?0:((gi>NGs-1)?NGs-1:gi);
        float w=fw1[gi*Hdim+c];
        #pragma unroll
        for(int t=0;t<TR;t++) acc[t]=fmaf(rbf[t][g],w,acc[t]);
    }
    __half* G=g_Gh+layer*NGRID*Hdim;
    #pragma unroll
    for(int t=0;t<TR;t++) G[(r0+t)*Hdim+c]=__float2half(gelu_f(acc[t]));
}

// --------------------------- tensor-core GEMM (full-K smem, one barrier)
template<bool GELU,bool RES,bool LAYERED,bool POOL,int MROWS>
__global__ void __launch_bounds__(256) k_tgemm(const __half* __restrict__ A,
                       const __half* __restrict__ W16,
                       const float* __restrict__ bias,
                       const float* __restrict__ Res,
                       float* __restrict__ Cf, __half* __restrict__ Ch,
                       const int* __restrict__ batch){
    extern __shared__ __align__(16) __half sm[];
    __half* As=sm;
    __half* Ws=sm+32*A_PAD;
    if(LAYERED){
        int L=blockIdx.z;
        A   += (size_t)L*MROWS*Hdim;
        W16 += (size_t)L*Hdim*Hdim;
        bias+= (size_t)L*Hdim;
        Ch  += (size_t)L*MROWS*Hdim;
    }
    int m0=blockIdx.x*32, n0=blockIdx.y*64;
    int tid=threadIdx.x;
    int wid=tid>>5, lane=tid&31;
    int wm=wid&1, wn=wid>>1;

    {
        int ar=tid>>3, ac=(tid&7)*8;
        #pragma unroll
        for(int p=0;p<4;p++){
            *reinterpret_cast<uint4*>(&As[ar*A_PAD + p*64 + ac]) =
                *reinterpret_cast<const uint4*>(&A[(size_t)(m0+ar)*Hdim + p*64 + ac]);
        }
        const __half* wrow=&W16[(size_t)tid*Hdim + n0];
        __half* srow=&Ws[tid*W_PAD];
        #pragma unroll
        for(int c=0;c<8;c++){
            *reinterpret_cast<uint4*>(&srow[c*8]) =
                *reinterpret_cast<const uint4*>(&wrow[c*8]);
        }
    }
    __syncthreads();

    float acc[2][4];
    #pragma unroll
    for(int nb=0;nb<2;nb++)
        #pragma unroll
        for(int q=0;q<4;q++) acc[nb][q]=0.f;

    unsigned a_base=smem_u32(&As[(wm*16 + (lane&7) + ((lane>>3)&1)*8)*A_PAD + ((lane>>4)&1)*8]);
    unsigned b_base=smem_u32(&Ws[((lane&7) + ((lane>>3)&1)*8)*W_PAD + wn*16 + ((lane>>4)&1)*8]);

    #pragma unroll
    for(int kc=0;kc<16;kc++){
        unsigned a0,a1,a2,a3, b0,b1,b2,b3;
        ldsm_x4 (a0,a1,a2,a3, a_base + kc*16*2);
        ldsm_x4t(b0,b1,b2,b3, b_base + kc*16*W_PAD*2);
        hmma(acc[0],a0,a1,a2,a3,b0,b1);
        hmma(acc[1],a0,a1,a2,a3,b2,b3);
    }

    int row0=m0 + wm*16 + (lane>>2);
    int row1=row0+8;
    #pragma unroll
    for(int nb=0;nb<2;nb++){
        int col=n0 + wn*16 + nb*8 + (lane&3)*2;
        float bz0=bias[col], bz1=bias[col+1];
        float x00=acc[nb][0]+bz0, x01=acc[nb][1]+bz1;
        float x10=acc[nb][2]+bz0, x11=acc[nb][3]+bz1;
        if(GELU){
            x00=gelu_f(x00); x01=gelu_f(x01);
            x10=gelu_f(x10); x11=gelu_f(x11);
        }
        if(RES){
            x00+=Res[(size_t)row0*Hdim+col]; x01+=Res[(size_t)row0*Hdim+col+1];
            x10+=Res[(size_t)row1*Hdim+col]; x11+=Res[(size_t)row1*Hdim+col+1];
            *reinterpret_cast<float2*>(&Cf[(size_t)row0*Hdim+col])=make_float2(x00,x01);
            *reinterpret_cast<float2*>(&Cf[(size_t)row1*Hdim+col])=make_float2(x10,x11);
            *reinterpret_cast<__half2*>(&g_hh[(size_t)row0*Hdim+col])=__floats2half2_rn(x00,x01);
            *reinterpret_cast<__half2*>(&g_hh[(size_t)row1*Hdim+col])=__floats2half2_rn(x10,x11);
            if(POOL){
                int b0r=batch[row0], b1r=batch[row1];
                atomicAdd(&g_pool[b0r*Hdim+col  ],x00);
                atomicAdd(&g_pool[b0r*Hdim+col+1],x01);
                atomicAdd(&g_pool[b1r*Hdim+col  ],x10);
                atomicAdd(&g_pool[b1r*Hdim+col+1],x11);
            }
        }else{
            *reinterpret_cast<__half2*>(&Ch[(size_t)row0*Hdim+col])=__floats2half2_rn(x00,x01);
            *reinterpret_cast<__half2*>(&Ch[(size_t)row1*Hdim+col])=__floats2half2_rn(x10,x11);
        }
    }
}

// ------------------- neighbor aggregation v3: balanced strips, 4 ch/thread
// 512 threads; 8 strips x 64 threads; atoms processed jointly (sequential).
__device__ __forceinline__ void agg_step4(unsigned p, uint2 hv,
                                          const __half2* __restrict__ tab_s,
                                          int c2, float2& a0, float2& a1){
    int r=(p>>10)&511;
    float f=(float)(p>>19)*(1.0f/4096.0f)-1.0f;
    float f2=f*f;
    __half2 al=__float2half2_rn(0.5f*(f2+f));
    __half2 be=__float2half2_rn(1.0f-f2);
    __half2 ga=__float2half2_rn(0.5f*(f2-f));
    const __half2* base=tab_s + r*128 + c2;
    uint2 mu=*reinterpret_cast<const uint2*>(base-128);
    uint2 zu=*reinterpret_cast<const uint2*>(base);
    uint2 qu=*reinterpret_cast<const uint2*>(base+128);
    __half2 m0=*reinterpret_cast<__half2*>(&mu.x), m1=*reinterpret_cast<__half2*>(&mu.y);
    __half2 z0=*reinterpret_cast<__half2*>(&zu.x), z1=*reinterpret_cast<__half2*>(&zu.y);
    __half2 q0=*reinterpret_cast<__half2*>(&qu.x), q1=*reinterpret_cast<__half2*>(&qu.y);
    __half2 h0=*reinterpret_cast<__half2*>(&hv.x), h1=*reinterpret_cast<__half2*>(&hv.y);
    __half2 w0=__hfma2(al,q0,__hfma2(be,z0,__hmul2(ga,m0)));
    __half2 w1=__hfma2(al,q1,__hfma2(be,z1,__hmul2(ga,m1)));
    float2 p0=__half22float2(__hmul2(w0,h0));
    float2 p1=__half22float2(__hmul2(w1,h1));
    a0.x+=p0.x; a0.y+=p0.y;
    a1.x+=p1.x; a1.y+=p1.y;
}

__global__ void __launch_bounds__(512,1) k_agg(const __half2* __restrict__ tab){
    extern __shared__ __half2 tab_s[];               // [NGRID*128] table
    float* red=reinterpret_cast<float*>(tab_s + NGRID*128);   // [8][256]
    int tid=threadIdx.x;
    {
        const uint4* src=reinterpret_cast<const uint4*>(tab);
        uint4* dst=reinterpret_cast<uint4*>(tab_s);
        #pragma unroll
        for(int idx=tid;idx<(NGRID*Hdim*2)/16;idx+=512) dst[idx]=src[idx];
    }
    __syncthreads();
    int strip=tid>>6;        // 0..7
    int c4=tid&63;           // 4-channel group
    int c2=c4*2;             // half2 index
    const uint2* __restrict__ hh=reinterpret_cast<const uint2*>(g_hh);
    for(int a=0;a<8;a++){
        int i=blockIdx.x*8+a;
        int total=g_cnt[i];
        const unsigned* __restrict__ lst=g_nbr+i*Natoms;
        int n0=(total*strip)>>3;
        int n1=(total*(strip+1))>>3;
        float2 a0=make_float2(0.f,0.f), a1=make_float2(0.f,0.f);
        int n=n0;
        for(; n+4<=n1; n+=4){
            unsigned p0=__ldg(lst+n+0);
            unsigned p1=__ldg(lst+n+1);
            unsigned p2=__ldg(lst+n+2);
            unsigned p3=__ldg(lst+n+3);
            uint2 h0=__ldg(hh+(p0&1023)*64+c4);
            uint2 h1=__ldg(hh+(p1&1023)*64+c4);
            uint2 h2=__ldg(hh+(p2&1023)*64+c4);
            uint2 h3=__ldg(hh+(p3&1023)*64+c4);
            agg_step4(p0,h0,tab_s,c2,a0,a1);
            agg_step4(p1,h1,tab_s,c2,a0,a1);
            agg_step4(p2,h2,tab_s,c2,a0,a1);
            agg_step4(p3,h3,tab_s,c2,a0,a1);
        }
        for(; n<n1; n++){
            unsigned p=__ldg(lst+n);
            uint2 hv=__ldg(hh+(p&1023)*64+c4);
            agg_step4(p,hv,tab_s,c2,a0,a1);
        }
        // strip partials -> smem
        float4 v=make_float4(a0.x,a0.y,a1.x,a1.y);
        *reinterpret_cast<float4*>(&red[strip*256 + c4*4])=v;
        __syncthreads();
        if(tid<128){
            float s0=0.f, s1=0.f;
            #pragma unroll
            for(int s=0;s<8;s++){
                float2 t=*reinterpret_cast<const float2*>(&red[s*256 + tid*2]);
                s0+=t.x; s1+=t.y;
            }
            reinterpret_cast<__half2*>(g_aggh)[i*128+tid]=__floats2half2_rn(s0,s1);
        }
        __syncthreads();
    }
}

// ------------------------------------------------- projection head + layernorm
__global__ void __launch_bounds__(512) k_head(
                       const float* __restrict__ pw1,const float* __restrict__ pb1,
                       const float* __restrict__ pw2,const float* __restrict__ pb2,
                       const float* __restrict__ lng,const float* __restrict__ lnb,
                       float* __restrict__ out){
    __shared__ float pv[Hdim];
    __shared__ float tv[Hdim];
    __shared__ float red[16];
    __shared__ float s_mu, s_inv;
    int b=blockIdx.x, tid=threadIdx.x;
    if(tid<Hdim) pv[tid]=g_pool[b*Hdim+tid];
    __syncthreads();
    if(tid<Hdim){
        float a=pb1[tid];
        for(int k=0;k<Hdim;k++) a=fmaf(pv[k],pw1[k*Hdim+tid],a);
        tv[tid]=gelu_f(a);
    }
    __syncthreads();
    float x=pb2[tid];
    for(int k=0;k<Hdim;k++) x=fmaf(tv[k],pw2[k*Ldim+tid],x);
    float sv=x;
    for(int d=16;d>0;d>>=1) sv+=__shfl_down_sync(0xffffffffu,sv,d);
    if((tid&31)==0) red[tid>>5]=sv;
    __syncthreads();
    if(tid==0){
        float t=0.f;
        #pragma unroll
        for(int w=0;w<16;w++) t+=red[w];
        s_mu=t/(float)Ldim;
    }
    __syncthreads();
    float mu=s_mu;
    float dv=x-mu;
    float s2=dv*dv;
    for(int d=16;d>0;d>>=1) s2+=__shfl_down_sync(0xffffffffu,s2,d);
    if((tid&31)==0) red[tid>>5]=s2;
    __syncthreads();
    if(tid==0){
        float t=0.f;
        #pragma unroll
        for(int w=0;w<16;w++) t+=red[w];
        s_inv=1.0f/sqrtf(t/(float)Ldim + 1e-5f);
    }
    __syncthreads();
    out[b*Ldim+tid]=(x-mu)*s_inv*lng[tid]+lnb[tid];
}

// ------------------------------------------------------------------ launcher
extern "C" void kernel_launch(void* const* d_in, const int* in_sizes, int n_in,
                              void* d_out, int out_size){
    const int*   z    =(const int*)  d_in[0];
    const float* pos  =(const float*)d_in[1];
    const int*   batch=(const int*)  d_in[2];
    const float* emb  =(const float*)d_in[3];
    const float* fw1  =(const float*)d_in[4];
    const float* fb1  =(const float*)d_in[5];
    const float* fw2  =(const float*)d_in[6];
    const float* fb2  =(const float*)d_in[7];
    const float* aw1  =(const float*)d_in[8];
    const float* ab1  =(const float*)d_in[9];
    const float* aw2  =(const float*)d_in[10];
    const float* ab2  =(const float*)d_in[11];
    const float* pw1  =(const float*)d_in[12];
    const float* pb1  =(const float*)d_in[13];
    const float* pw2  =(const float*)d_in[14];
    const float* pb2  =(const float*)d_in[15];
    const float* lng  =(const float*)d_in[16];
    const float* lnb  =(const float*)d_in[17];
    float* out=(float*)d_out;

    float *ph;
    __half *ptab,*pGh,*paggh,*ptmph,*pfw2h,*paw1h,*paw2h;
    cudaGetSymbolAddress((void**)&ph,   g_h);
    cudaGetSymbolAddress((void**)&ptab, g_tab);
    cudaGetSymbolAddress((void**)&pGh,  g_Gh);
    cudaGetSymbolAddress((void**)&paggh,g_aggh);
    cudaGetSymbolAddress((void**)&ptmph,g_tmph);
    cudaGetSymbolAddress((void**)&pfw2h,g_fw2h);
    cudaGetSymbolAddress((void**)&paw1h,g_aw1h);
    cudaGetSymbolAddress((void**)&paw2h,g_aw2h);

    cudaFuncSetAttribute(k_agg, cudaFuncAttributeMaxDynamicSharedMemorySize, AGG_SMEM);
    cudaFuncSetAttribute((const void*)k_tgemm<false,false,true ,false,NGRID>,
                         cudaFuncAttributeMaxDynamicSharedMemorySize, GEMM_SMEM);
    cudaFuncSetAttribute((const void*)k_tgemm<true ,false,false,false,Natoms>,
                         cudaFuncAttributeMaxDynamicSharedMemorySize, GEMM_SMEM);
    cudaFuncSetAttribute((const void*)k_tgemm<false,true ,false,false,Natoms>,
                         cudaFuncAttributeMaxDynamicSharedMemorySize, GEMM_SMEM);
    cudaFuncSetAttribute((const void*)k_tgemm<false,true ,false,true ,Natoms>,
                         cudaFuncAttributeMaxDynamicSharedMemorySize, GEMM_SMEM);

    k_prep<<<Natoms+768+16,256>>>(z,emb,fw2,aw1,aw2);
    k_nbr<<<Natoms,256>>>(pos);
    k_hidden<<<dim3(NGRID/TR,NIs),Hdim>>>(fw1,fb1);
    k_tgemm<false,false,true ,false,NGRID><<<dim3(NGRID/32,Hdim/64,NIs),256,GEMM_SMEM>>>(pGh, pfw2h, fb2, nullptr, nullptr, ptab, nullptr);
    for(int l=0;l<NIs;l++){
        k_agg<<<Natoms/8,512,AGG_SMEM>>>(reinterpret_cast<const __half2*>(ptab)+(size_t)l*NGRID*Hdim/2);
        k_tgemm<true ,false,false,false,Natoms><<<dim3(Natoms/32,Hdim/64),256,GEMM_SMEM>>>(paggh, paw1h+(size_t)l*Hdim*Hdim, ab1+l*Hdim, nullptr, nullptr, ptmph, nullptr);
        if(l<NIs-1)
            k_tgemm<false,true ,false,false,Natoms><<<dim3(Natoms/32,Hdim/64),256,GEMM_SMEM>>>(ptmph, paw2h+(size_t)l*Hdim*Hdim, ab2+l*Hdim, ph, ph, nullptr, nullptr);
        else
            k_tgemm<false,true ,false,true ,Natoms><<<dim3(Natoms/32,Hdim/64),256,GEMM_SMEM>>>(ptmph, paw2h+(size_t)l*Hdim*Hdim, ab2+l*Hdim, ph, ph, nullptr, batch);
    }
    k_head<<<Bmol,512>>>(pw1,pb1,pw2,pb2,lng,lnb,out);
}